// round 4
// baseline (speedup 1.0000x reference)
#include <cuda_runtime.h>
#include <math.h>

#define LSEQ 4096
#define NHQ 8
#define NKV 4
#define DH 256
#define HID 2304
#define WIN 2048
#define QDIM (NHQ*DH)   /* 2048 */
#define KDIM (NKV*DH)   /* 1024 */

static __device__ float g_q[(size_t)LSEQ * QDIM];
static __device__ float g_k[(size_t)LSEQ * KDIM];
static __device__ float g_v[(size_t)LSEQ * KDIM];
static __device__ float g_att[(size_t)LSEQ * QDIM];
static __device__ float g_vsum[KDIM];
static __device__ float g_cos[(size_t)LSEQ * 128];
static __device__ float g_sin[(size_t)LSEQ * 128];

#define SCALEF 0.05892556509887896f   /* 288^-0.5 */
#define NEGC  (-1.0e9f)

// ---------------------------------------------------------------------------
// fp32 tiled GEMM: C[M,N] = A[M,K] @ B[K,N], row-major. BM=BN=64, BK=16,
// 256 threads, 4x4 microtile.
// ---------------------------------------------------------------------------
__global__ __launch_bounds__(256) void gemm_kernel(
    const float* __restrict__ A, const float* __restrict__ B,
    float* __restrict__ C, int M, int N, int K)
{
    __shared__ float As[16][65];
    __shared__ float Bs[16][64];
    const int tid  = threadIdx.x;
    const int row0 = blockIdx.y * 64;
    const int col0 = blockIdx.x * 64;
    const int ty = tid >> 4, tx = tid & 15;

    const int ar  = tid >> 2;      // 0..63
    const int ac4 = tid & 3;       // 0..3 (float4 along K)
    const int br  = tid >> 4;      // 0..15
    const int bc4 = tid & 15;      // 0..15 (float4 along N)

    float acc[4][4];
#pragma unroll
    for (int i = 0; i < 4; i++)
#pragma unroll
        for (int j = 0; j < 4; j++) acc[i][j] = 0.0f;

    for (int k0 = 0; k0 < K; k0 += 16) {
        float4 av = *(const float4*)(A + (size_t)(row0 + ar) * K + k0 + ac4 * 4);
        float4 bv = *(const float4*)(B + (size_t)(k0 + br) * N + col0 + bc4 * 4);
        As[ac4 * 4 + 0][ar] = av.x;
        As[ac4 * 4 + 1][ar] = av.y;
        As[ac4 * 4 + 2][ar] = av.z;
        As[ac4 * 4 + 3][ar] = av.w;
        *(float4*)(&Bs[br][bc4 * 4]) = bv;
        __syncthreads();
#pragma unroll
        for (int kk = 0; kk < 16; kk++) {
            float a[4], b[4];
#pragma unroll
            for (int i = 0; i < 4; i++) a[i] = As[kk][ty + 16 * i];
#pragma unroll
            for (int j = 0; j < 4; j++) b[j] = Bs[kk][tx + 16 * j];
#pragma unroll
            for (int i = 0; i < 4; i++)
#pragma unroll
                for (int j = 0; j < 4; j++)
                    acc[i][j] = fmaf(a[i], b[j], acc[i][j]);
        }
        __syncthreads();
    }
#pragma unroll
    for (int i = 0; i < 4; i++)
#pragma unroll
        for (int j = 0; j < 4; j++)
            C[(size_t)(row0 + ty + 16 * i) * N + col0 + tx + 16 * j] = acc[i][j];
}

// ---------------------------------------------------------------------------
// RoPE tables: angle = fl32(l * invf), invf = fl32(1/10000^(2i/256)).
// cos/sin of the fp32 angle evaluated in DOUBLE: immune to --use_fast_math.
// (__sincosf's fast range reduction is invalid beyond ~100 rad; angles here
// reach 4096 rad -> this was the rel_err=0.695 root cause.)
// ---------------------------------------------------------------------------
__global__ void rope_table_kernel()
{
    int idx = blockIdx.x * blockDim.x + threadIdx.x;
    if (idx >= LSEQ * 128) return;
    int i = idx & 127;
    int l = idx >> 7;
    double ex   = (double)(2 * i) / 256.0;
    float  pf   = (float)pow(10000.0, ex);       // fp32-rounded pow, as in jax
    float  invf = __fdiv_rn(1.0f, pf);           // IEEE fp32 reciprocal
    float  ang  = (float)l * invf;               // fp32 product (jnp.outer)
    double a = (double)ang;
    g_cos[idx] = (float)cos(a);
    g_sin[idx] = (float)sin(a);
}

__global__ void rope_apply_kernel(float* __restrict__ buf, int nheads)
{
    int l = blockIdx.x;        // 0..4095
    int i = threadIdx.x;       // 0..127
    float c = g_cos[(size_t)l * 128 + i];
    float s = g_sin[(size_t)l * 128 + i];
    for (int h = 0; h < nheads; h++) {
        size_t base = (size_t)l * nheads * DH + (size_t)h * DH;
        float x1 = buf[base + i];
        float x2 = buf[base + i + 128];
        buf[base + i]       = x1 * c - x2 * s;
        buf[base + i + 128] = x2 * c + x1 * s;
    }
}

// ---------------------------------------------------------------------------
// Per-kv-head-dim sum of V over keys k < WIN (the window-masked columns).
// ---------------------------------------------------------------------------
__global__ void vsum_kernel()
{
    int idx = blockIdx.x * blockDim.x + threadIdx.x;  // 0..1023 = hkv*256+d
    if (idx >= KDIM) return;
    float s = 0.0f;
    for (int l = 0; l < WIN; l++)
        s += g_v[(size_t)l * KDIM + idx];
    g_vsum[idx] = s;
}

// ---------------------------------------------------------------------------
// Accurate 50*tanh(x/50) via expm1f (no fast-math substitution).
// ---------------------------------------------------------------------------
__device__ __forceinline__ float softcap50(float s)
{
    float x = __fdiv_rn(s * SCALEF, 50.0f);
    x = fminf(fmaxf(x, -15.0f), 15.0f);          // tanh saturated beyond
    float e = expm1f(2.0f * x);
    return 50.0f * __fdiv_rn(e, e + 2.0f);
}

// ---------------------------------------------------------------------------
// Flash attention with the reference's exact fp32 masking semantics:
//  q >= 2048: softmax over k in [2048, q]. Skipped keys (k<2048 exactly -1e9,
//             k>q at fl(t-1e9)) give exp(a-m) <= exp(-1e9+114) -> exactly 0.0f
//             in fp32, so skipping them is bit-identical.
//  q <  2048: columns k<2048 are exactly -1e9 (window-override); folded in as
//             initial online-softmax state m=-1e9, l=2048, O=Vsum. Columns
//             k in [2048,4096) computed literally as a = fl(t + (-1e9)).
// Block: 32 queries x 1 head, 256 threads, key tiles of 32.
// ---------------------------------------------------------------------------
__global__ __launch_bounds__(256) void flash_kernel()
{
    extern __shared__ float sm[];
    float* QsT = sm;                 // [256][33] transposed Q tile
    float* KsT = QsT + 256 * 33;     // [256][33] transposed K tile
    float* Vs  = KsT + 256 * 33;     // [32][260] natural V tile
    float* Ss  = Vs + 32 * 260;      // [32][33] scores / probs
    float* m_s = Ss + 32 * 33;       // [32]
    float* l_s = m_s + 32;           // [32]
    float* c_s = l_s + 32;           // [32]

    const int tid = threadIdx.x;
    const int h   = blockIdx.y;
    const int hkv = h >> 1;          // repeat_interleave GQA mapping
    const int q0  = blockIdx.x * 32;
    const bool lowq = (q0 < WIN);
    const int ty = tid >> 4, tx = tid & 15;
    const int r0 = 2 * ty, r1 = r0 + 1;

    for (int i = tid; i < 32 * 64; i += 256) {
        int r = i >> 6, c4 = i & 63;
        float4 v4 = *(const float4*)(g_q + (size_t)(q0 + r) * QDIM + h * DH + c4 * 4);
        int d = c4 * 4;
        QsT[(d + 0) * 33 + r] = v4.x;
        QsT[(d + 1) * 33 + r] = v4.y;
        QsT[(d + 2) * 33 + r] = v4.z;
        QsT[(d + 3) * 33 + r] = v4.w;
    }
    if (tid < 32) {
        m_s[tid] = lowq ? NEGC : -INFINITY;
        l_s[tid] = lowq ? 2048.0f : 0.0f;
    }
    float acc0[16], acc1[16];
#pragma unroll
    for (int c = 0; c < 16; c++) {
        float v = lowq ? g_vsum[hkv * DH + tx + 16 * c] : 0.0f;
        acc0[c] = v;
        acc1[c] = v;
    }

    const int kend = lowq ? LSEQ : (q0 + 32);
    for (int k0 = WIN; k0 < kend; k0 += 32) {
        __syncthreads();
        for (int i = tid; i < 32 * 64; i += 256) {
            int r = i >> 6, c4 = i & 63;
            size_t gb = (size_t)(k0 + r) * KDIM + hkv * DH + c4 * 4;
            float4 kv = *(const float4*)(g_k + gb);
            int d = c4 * 4;
            KsT[(d + 0) * 33 + r] = kv.x;
            KsT[(d + 1) * 33 + r] = kv.y;
            KsT[(d + 2) * 33 + r] = kv.z;
            KsT[(d + 3) * 33 + r] = kv.w;
            float4 vv = *(const float4*)(g_v + gb);
            *(float4*)(Vs + r * 260 + c4 * 4) = vv;
        }
        __syncthreads();

        float s00 = 0.f, s01 = 0.f, s10 = 0.f, s11 = 0.f;
#pragma unroll 8
        for (int d = 0; d < 256; d++) {
            float a0 = QsT[d * 33 + r0];
            float a1 = QsT[d * 33 + r1];
            float b0 = KsT[d * 33 + tx];
            float b1 = KsT[d * 33 + tx + 16];
            s00 = fmaf(a0, b0, s00);
            s01 = fmaf(a0, b1, s01);
            s10 = fmaf(a1, b0, s10);
            s11 = fmaf(a1, b1, s11);
        }
        float t00 = softcap50(s00);
        float t01 = softcap50(s01);
        float t10 = softcap50(s10);
        float t11 = softcap50(s11);

        float a00, a01, a10, a11;
        if (lowq) {
            // all these keys are > q: causal mask adds -1e9 in fp32
            a00 = t00 + NEGC;
            a01 = t01 + NEGC;
            a10 = t10 + NEGC;
            a11 = t11 + NEGC;
        } else {
            a00 = (k0 + tx      > q0 + r0) ? NEGC : t00;
            a01 = (k0 + tx + 16 > q0 + r0) ? NEGC : t01;
            a10 = (k0 + tx      > q0 + r1) ? NEGC : t10;
            a11 = (k0 + tx + 16 > q0 + r1) ? NEGC : t11;
        }
        Ss[r0 * 33 + tx]      = a00;
        Ss[r0 * 33 + tx + 16] = a01;
        Ss[r1 * 33 + tx]      = a10;
        Ss[r1 * 33 + tx + 16] = a11;
        __syncthreads();

        if (tid < 32) {
            float* row = Ss + tid * 33;
            float mo = m_s[tid];
            float mx = mo;
#pragma unroll
            for (int j = 0; j < 32; j++) mx = fmaxf(mx, row[j]);
            float corr = expf(mo - mx);
            float l = l_s[tid] * corr;
#pragma unroll
            for (int j = 0; j < 32; j++) {
                float pv = expf(row[j] - mx);
                row[j] = pv;
                l += pv;
            }
            m_s[tid] = mx;
            l_s[tid] = l;
            c_s[tid] = corr;
        }
        __syncthreads();

        float cr0 = c_s[r0], cr1 = c_s[r1];
#pragma unroll
        for (int c = 0; c < 16; c++) { acc0[c] *= cr0; acc1[c] *= cr1; }
        const float* pr0 = Ss + r0 * 33;
        const float* pr1 = Ss + r1 * 33;
        for (int j = 0; j < 32; j++) {
            float p0 = pr0[j], p1 = pr1[j];
            const float* vr = Vs + j * 260 + tx;
#pragma unroll
            for (int c = 0; c < 16; c++) {
                float vv = vr[16 * c];
                acc0[c] = fmaf(p0, vv, acc0[c]);
                acc1[c] = fmaf(p1, vv, acc1[c]);
            }
        }
    }

    float li0 = l_s[r0], li1 = l_s[r1];
    size_t ob0 = (size_t)(q0 + r0) * QDIM + h * DH + tx;
    size_t ob1 = (size_t)(q0 + r1) * QDIM + h * DH + tx;
#pragma unroll
    for (int c = 0; c < 16; c++) {
        g_att[ob0 + 16 * c] = __fdiv_rn(acc0[c], li0);
        g_att[ob1 + 16 * c] = __fdiv_rn(acc1[c], li1);
    }
}

// ---------------------------------------------------------------------------
extern "C" void kernel_launch(void* const* d_in, const int* in_sizes, int n_in,
                              void* d_out, int out_size)
{
    // Positional mapping in metadata (dict) order — validated by round-0/2
    // runs completing without fault: x, mask, wq, wk, wv, wo.
    const float* x  = (const float*)d_in[0];
    // d_in[1] = mask (recomputed analytically; unused)
    const float* wq = (const float*)d_in[2];
    const float* wk = (const float*)d_in[3];
    const float* wv = (const float*)d_in[4];
    const float* wo = (const float*)d_in[5];
    float* out = (float*)d_out;

    float *pq, *pk, *pv, *patt;
    cudaGetSymbolAddress((void**)&pq,   g_q);
    cudaGetSymbolAddress((void**)&pk,   g_k);
    cudaGetSymbolAddress((void**)&pv,   g_v);
    cudaGetSymbolAddress((void**)&patt, g_att);

    dim3 blk(256);

    // QKV projections
    gemm_kernel<<<dim3(QDIM / 64, LSEQ / 64), blk>>>(x, wq, pq, LSEQ, QDIM, HID);
    gemm_kernel<<<dim3(KDIM / 64, LSEQ / 64), blk>>>(x, wk, pk, LSEQ, KDIM, HID);
    gemm_kernel<<<dim3(KDIM / 64, LSEQ / 64), blk>>>(x, wv, pv, LSEQ, KDIM, HID);

    // RoPE tables (double trig, fast-math immune) + apply
    rope_table_kernel<<<(LSEQ * 128 + 255) / 256, blk>>>();
    rope_apply_kernel<<<LSEQ, 128>>>(pq, NHQ);
    rope_apply_kernel<<<LSEQ, 128>>>(pk, NKV);

    // V column sums over k < WIN
    vsum_kernel<<<(KDIM + 255) / 256, blk>>>();

    // Flash attention
    const int FLASH_SMEM = (256 * 33 * 2 + 32 * 260 + 32 * 33 + 96) * 4; // 105472 B
    cudaFuncSetAttribute(flash_kernel,
                         cudaFuncAttributeMaxDynamicSharedMemorySize, FLASH_SMEM);
    flash_kernel<<<dim3(LSEQ / 32, NHQ), blk, FLASH_SMEM>>>();

    // Output projection
    gemm_kernel<<<dim3(HID / 64, LSEQ / 64), blk>>>(patt, wo, out, LSEQ, HID, QDIM);
}

// round 5
// speedup vs baseline: 1.5471x; 1.5471x over previous
#include <cuda_runtime.h>
#include <math.h>

#define LSEQ 4096
#define NHQ 8
#define NKV 4
#define DH 256
#define HID 2304
#define WIN 2048
#define QDIM (NHQ*DH)   /* 2048 */
#define KDIM (NKV*DH)   /* 1024 */

static __device__ float g_q[(size_t)LSEQ * QDIM];
static __device__ float g_k[(size_t)LSEQ * KDIM];
static __device__ float g_v[(size_t)LSEQ * KDIM];
static __device__ float g_att[(size_t)LSEQ * QDIM];
static __device__ float g_vmean[KDIM];
static __device__ float g_cos[(size_t)LSEQ * 128];
static __device__ float g_sin[(size_t)LSEQ * 128];

#define SCALEF 0.05892556509887896f   /* 288^-0.5 */
#define NEGC  (-1.0e9f)

// ---------------------------------------------------------------------------
// fp32 tiled GEMM: C[M,N] = A[M,K] @ B[K,N], row-major.
// BM=BN=128, BK=16, 256 threads, 8x8 microtile (FMA-bound: 64 FMA per
// 4 LDS.128). Requires M%128==0, N%128==0, K%16==0 (all shapes here comply).
// ---------------------------------------------------------------------------
__global__ __launch_bounds__(256) void gemm128(
    const float* __restrict__ A, const float* __restrict__ B,
    float* __restrict__ C, int M, int N, int K)
{
    __shared__ float As[16][132];   // [k][m], 132*4=528B row = 16B aligned
    __shared__ float Bs[16][128];
    const int tid  = threadIdx.x;
    const int row0 = blockIdx.y * 128;
    const int col0 = blockIdx.x * 128;
    const int ty = tid >> 4, tx = tid & 15;

    float acc[8][8];
#pragma unroll
    for (int i = 0; i < 8; i++)
#pragma unroll
        for (int j = 0; j < 8; j++) acc[i][j] = 0.0f;

    for (int k0 = 0; k0 < K; k0 += 16) {
#pragma unroll
        for (int l = 0; l < 2; l++) {
            int idx = tid + l * 256;
            int ar = idx >> 2, ac = idx & 3;          // A: 128 rows x 4 float4
            float4 av = *(const float4*)(A + (size_t)(row0 + ar) * K + k0 + ac * 4);
            As[ac * 4 + 0][ar] = av.x;
            As[ac * 4 + 1][ar] = av.y;
            As[ac * 4 + 2][ar] = av.z;
            As[ac * 4 + 3][ar] = av.w;
            int br = idx >> 5, bc = idx & 31;         // B: 16 rows x 32 float4
            *(float4*)(&Bs[br][bc * 4]) =
                *(const float4*)(B + (size_t)(k0 + br) * N + col0 + bc * 4);
        }
        __syncthreads();
#pragma unroll
        for (int kk = 0; kk < 16; kk++) {
            float a[8], b[8];
            *(float4*)(a)     = *(const float4*)(&As[kk][ty * 4]);
            *(float4*)(a + 4) = *(const float4*)(&As[kk][ty * 4 + 64]);
            *(float4*)(b)     = *(const float4*)(&Bs[kk][tx * 4]);
            *(float4*)(b + 4) = *(const float4*)(&Bs[kk][tx * 4 + 64]);
#pragma unroll
            for (int i = 0; i < 8; i++)
#pragma unroll
                for (int j = 0; j < 8; j++)
                    acc[i][j] = fmaf(a[i], b[j], acc[i][j]);
        }
        __syncthreads();
    }
#pragma unroll
    for (int i = 0; i < 8; i++) {
        int r = row0 + ((i < 4) ? (ty * 4 + i) : (64 + ty * 4 + i - 4));
        float4 v0 = make_float4(acc[i][0], acc[i][1], acc[i][2], acc[i][3]);
        float4 v1 = make_float4(acc[i][4], acc[i][5], acc[i][6], acc[i][7]);
        *(float4*)(C + (size_t)r * N + col0 + tx * 4) = v0;
        *(float4*)(C + (size_t)r * N + col0 + 64 + tx * 4) = v1;
    }
}

// ---------------------------------------------------------------------------
// RoPE tables: angle = fl32(l * invf); cos/sin evaluated in DOUBLE (immune to
// --use_fast_math; __sincosf is invalid at ~4000 rad — R0-R2 root cause).
// ---------------------------------------------------------------------------
__global__ void rope_table_kernel()
{
    int idx = blockIdx.x * blockDim.x + threadIdx.x;
    if (idx >= LSEQ * 128) return;
    int i = idx & 127;
    int l = idx >> 7;
    double ex   = (double)(2 * i) / 256.0;
    float  pf   = (float)pow(10000.0, ex);
    float  invf = __fdiv_rn(1.0f, pf);
    float  ang  = (float)l * invf;
    double a = (double)ang;
    g_cos[idx] = (float)cos(a);
    g_sin[idx] = (float)sin(a);
}

__global__ void rope_apply_kernel(float* __restrict__ buf, int nheads)
{
    int l = blockIdx.x;
    int i = threadIdx.x;
    float c = g_cos[(size_t)l * 128 + i];
    float s = g_sin[(size_t)l * 128 + i];
    for (int h = 0; h < nheads; h++) {
        size_t base = (size_t)l * nheads * DH + (size_t)h * DH;
        float x1 = buf[base + i];
        float x2 = buf[base + i + 128];
        buf[base + i]       = x1 * c - x2 * s;
        buf[base + i + 128] = x2 * c + x1 * s;
    }
}

// ---------------------------------------------------------------------------
// Mean of V over ALL 4096 keys, double accumulation (for q<2048 rows, whose
// attention weights are all exactly 1/4096 — see masking analysis).
// ---------------------------------------------------------------------------
__global__ void vmean_kernel()
{
    int idx = blockIdx.x * blockDim.x + threadIdx.x;
    if (idx >= KDIM) return;
    double s = 0.0;
    for (int l = 0; l < LSEQ; l++)
        s += (double)g_v[(size_t)l * KDIM + idx];
    g_vmean[idx] = (float)(s * (1.0 / 4096.0));
}

// Fill all q<2048 attention-output rows with the per-head V mean.
__global__ void lowq_fill_kernel()
{
    int idx = blockIdx.x * blockDim.x + threadIdx.x;   // 2048*2048 outputs
    if (idx >= WIN * QDIM) return;
    int col = idx & (QDIM - 1);
    int h = col >> 8;
    int d = col & 255;
    g_att[idx] = g_vmean[(h >> 1) * 256 + d];
}

// ---------------------------------------------------------------------------
// Accurate 50*tanh(x/50) via expm1f (no fast-math substitution).
// ---------------------------------------------------------------------------
__device__ __forceinline__ float softcap50(float s)
{
    float x = __fdiv_rn(s * SCALEF, 50.0f);
    x = fminf(fmaxf(x, -15.0f), 15.0f);
    float e = expm1f(2.0f * x);
    return 50.0f * __fdiv_rn(e, e + 2.0f);
}

// ---------------------------------------------------------------------------
// Flash attention for q >= 2048 only: softmax over k in [2048, q].
// Keys k<2048 (exactly -1e9) and k>q (fl(t-1e9)) give exp(a-m) <= 
// exp(-1e9+114) -> exactly 0.0f, so skipping them is bit-identical.
// Block: 32 queries x 1 head; blockIdx.x mapped to DESCENDING q0 so the
// heaviest blocks (most key tiles) launch in the first wave.
// ---------------------------------------------------------------------------
__global__ __launch_bounds__(256) void flash_kernel()
{
    extern __shared__ float sm[];
    float* QsT = sm;                 // [256][33] transposed Q tile
    float* KsT = QsT + 256 * 33;     // [256][33] transposed K tile
    float* Vs  = KsT + 256 * 33;     // [32][260] natural V tile
    float* Ss  = Vs + 32 * 260;      // [32][33] scores / probs
    float* m_s = Ss + 32 * 33;       // [32]
    float* l_s = m_s + 32;           // [32]
    float* c_s = l_s + 32;           // [32]

    const int tid = threadIdx.x;
    const int h   = blockIdx.y;
    const int hkv = h >> 1;
    const int q0  = WIN + (63 - (int)blockIdx.x) * 32;   // descending work
    const int ty = tid >> 4, tx = tid & 15;
    const int r0 = 2 * ty, r1 = r0 + 1;

    for (int i = tid; i < 32 * 64; i += 256) {
        int r = i >> 6, c4 = i & 63;
        float4 v4 = *(const float4*)(g_q + (size_t)(q0 + r) * QDIM + h * DH + c4 * 4);
        int d = c4 * 4;
        QsT[(d + 0) * 33 + r] = v4.x;
        QsT[(d + 1) * 33 + r] = v4.y;
        QsT[(d + 2) * 33 + r] = v4.z;
        QsT[(d + 3) * 33 + r] = v4.w;
    }
    if (tid < 32) {
        m_s[tid] = -INFINITY;
        l_s[tid] = 0.0f;
    }
    float acc0[16], acc1[16];
#pragma unroll
    for (int c = 0; c < 16; c++) { acc0[c] = 0.0f; acc1[c] = 0.0f; }

    const int kend = q0 + 32;
    for (int k0 = WIN; k0 < kend; k0 += 32) {
        __syncthreads();
        for (int i = tid; i < 32 * 64; i += 256) {
            int r = i >> 6, c4 = i & 63;
            size_t gb = (size_t)(k0 + r) * KDIM + hkv * DH + c4 * 4;
            float4 kv = *(const float4*)(g_k + gb);
            int d = c4 * 4;
            KsT[(d + 0) * 33 + r] = kv.x;
            KsT[(d + 1) * 33 + r] = kv.y;
            KsT[(d + 2) * 33 + r] = kv.z;
            KsT[(d + 3) * 33 + r] = kv.w;
            float4 vv = *(const float4*)(g_v + gb);
            *(float4*)(Vs + r * 260 + c4 * 4) = vv;
        }
        __syncthreads();

        float s00 = 0.f, s01 = 0.f, s10 = 0.f, s11 = 0.f;
#pragma unroll 8
        for (int d = 0; d < 256; d++) {
            float a0 = QsT[d * 33 + r0];
            float a1 = QsT[d * 33 + r1];
            float b0 = KsT[d * 33 + tx];
            float b1 = KsT[d * 33 + tx + 16];
            s00 = fmaf(a0, b0, s00);
            s01 = fmaf(a0, b1, s01);
            s10 = fmaf(a1, b0, s10);
            s11 = fmaf(a1, b1, s11);
        }
        float t00 = softcap50(s00);
        float t01 = softcap50(s01);
        float t10 = softcap50(s10);
        float t11 = softcap50(s11);

        float a00 = (k0 + tx      > q0 + r0) ? NEGC : t00;
        float a01 = (k0 + tx + 16 > q0 + r0) ? NEGC : t01;
        float a10 = (k0 + tx      > q0 + r1) ? NEGC : t10;
        float a11 = (k0 + tx + 16 > q0 + r1) ? NEGC : t11;

        Ss[r0 * 33 + tx]      = a00;
        Ss[r0 * 33 + tx + 16] = a01;
        Ss[r1 * 33 + tx]      = a10;
        Ss[r1 * 33 + tx + 16] = a11;
        __syncthreads();

        if (tid < 32) {
            float* row = Ss + tid * 33;
            float mo = m_s[tid];
            float mx = mo;
#pragma unroll
            for (int j = 0; j < 32; j++) mx = fmaxf(mx, row[j]);
            float corr = expf(mo - mx);
            float l = l_s[tid] * corr;
#pragma unroll
            for (int j = 0; j < 32; j++) {
                float pv = expf(row[j] - mx);
                row[j] = pv;
                l += pv;
            }
            m_s[tid] = mx;
            l_s[tid] = l;
            c_s[tid] = corr;
        }
        __syncthreads();

        float cr0 = c_s[r0], cr1 = c_s[r1];
#pragma unroll
        for (int c = 0; c < 16; c++) { acc0[c] *= cr0; acc1[c] *= cr1; }
        const float* pr0 = Ss + r0 * 33;
        const float* pr1 = Ss + r1 * 33;
        for (int j = 0; j < 32; j++) {
            float p0 = pr0[j], p1 = pr1[j];
            const float* vr = Vs + j * 260 + tx;
#pragma unroll
            for (int c = 0; c < 16; c++) {
                float vv = vr[16 * c];
                acc0[c] = fmaf(p0, vv, acc0[c]);
                acc1[c] = fmaf(p1, vv, acc1[c]);
            }
        }
    }

    float li0 = l_s[r0], li1 = l_s[r1];
    size_t ob0 = (size_t)(q0 + r0) * QDIM + h * DH + tx;
    size_t ob1 = (size_t)(q0 + r1) * QDIM + h * DH + tx;
#pragma unroll
    for (int c = 0; c < 16; c++) {
        g_att[ob0 + 16 * c] = __fdiv_rn(acc0[c], li0);
        g_att[ob1 + 16 * c] = __fdiv_rn(acc1[c], li1);
    }
}

// ---------------------------------------------------------------------------
extern "C" void kernel_launch(void* const* d_in, const int* in_sizes, int n_in,
                              void* d_out, int out_size)
{
    // Positional mapping (metadata/dict order): x, mask, wq, wk, wv, wo.
    const float* x  = (const float*)d_in[0];
    const float* wq = (const float*)d_in[2];
    const float* wk = (const float*)d_in[3];
    const float* wv = (const float*)d_in[4];
    const float* wo = (const float*)d_in[5];
    float* out = (float*)d_out;

    float *pq, *pk, *pv, *patt;
    cudaGetSymbolAddress((void**)&pq,   g_q);
    cudaGetSymbolAddress((void**)&pk,   g_k);
    cudaGetSymbolAddress((void**)&pv,   g_v);
    cudaGetSymbolAddress((void**)&patt, g_att);

    dim3 blk(256);

    // QKV projections (128x128 tiles)
    gemm128<<<dim3(QDIM / 128, LSEQ / 128), blk>>>(x, wq, pq, LSEQ, QDIM, HID);
    gemm128<<<dim3(KDIM / 128, LSEQ / 128), blk>>>(x, wk, pk, LSEQ, KDIM, HID);
    gemm128<<<dim3(KDIM / 128, LSEQ / 128), blk>>>(x, wv, pv, LSEQ, KDIM, HID);

    // RoPE tables + apply
    rope_table_kernel<<<(LSEQ * 128 + 255) / 256, blk>>>();
    rope_apply_kernel<<<LSEQ, 128>>>(pq, NHQ);
    rope_apply_kernel<<<LSEQ, 128>>>(pk, NKV);

    // V mean over all keys (double accum) + broadcast to all q<2048 rows
    vmean_kernel<<<(KDIM + 255) / 256, blk>>>();
    lowq_fill_kernel<<<(WIN * QDIM + 255) / 256, blk>>>();

    // Flash attention, q >= 2048 only, heaviest blocks first
    const int FLASH_SMEM = (256 * 33 * 2 + 32 * 260 + 32 * 33 + 96) * 4;
    cudaFuncSetAttribute(flash_kernel,
                         cudaFuncAttributeMaxDynamicSharedMemorySize, FLASH_SMEM);
    flash_kernel<<<dim3(64, NHQ), blk, FLASH_SMEM>>>();

    // Output projection
    gemm128<<<dim3(HID / 128, LSEQ / 128), blk>>>(patt, wo, out, LSEQ, HID, QDIM);
}

// round 7
// speedup vs baseline: 2.1383x; 1.3821x over previous
#include <cuda_runtime.h>
#include <cuda_bf16.h>
#include <math.h>
#include <stdint.h>

#define LSEQ 4096
#define NHQ 8
#define NKV 4
#define DH 256
#define HID 2304
#define WIN 2048
#define QDIM (NHQ*DH)   /* 2048 */
#define KDIM (NKV*DH)   /* 1024 */

#define SCALEF 0.05892556509887896f   /* 288^-0.5 */
#define NEGC  (-1.0e9f)

// fp32 intermediates
static __device__ float g_q[(size_t)LSEQ * QDIM];
static __device__ float g_k[(size_t)LSEQ * KDIM];
static __device__ float g_v[(size_t)LSEQ * KDIM];
static __device__ float g_att[(size_t)LSEQ * QDIM];
static __device__ float g_vmean[KDIM];
static __device__ float g_cos[(size_t)LSEQ * 128];
static __device__ float g_sin[(size_t)LSEQ * 128];

// bf16-split operands
static __device__ __nv_bfloat16 g_xhi[(size_t)LSEQ * HID];
static __device__ __nv_bfloat16 g_xlo[(size_t)LSEQ * HID];
static __device__ __nv_bfloat16 g_ahi[(size_t)LSEQ * QDIM];
static __device__ __nv_bfloat16 g_alo[(size_t)LSEQ * QDIM];
// weights transposed to [N][K] K-major
static __device__ __nv_bfloat16 g_wqhi[(size_t)QDIM * HID];
static __device__ __nv_bfloat16 g_wqlo[(size_t)QDIM * HID];
static __device__ __nv_bfloat16 g_wkhi[(size_t)KDIM * HID];
static __device__ __nv_bfloat16 g_wklo[(size_t)KDIM * HID];
static __device__ __nv_bfloat16 g_wvhi[(size_t)KDIM * HID];
static __device__ __nv_bfloat16 g_wvlo[(size_t)KDIM * HID];
static __device__ __nv_bfloat16 g_wohi[(size_t)HID * QDIM];
static __device__ __nv_bfloat16 g_wolo[(size_t)HID * QDIM];

// ===========================================================================
// Helpers (base-target PTX only: ldmatrix / mma.sync / cp.async)
// ===========================================================================
__device__ __forceinline__ uint32_t smem_u32(const void* p) {
    uint32_t r;
    asm("{ .reg .u64 t; cvta.to.shared.u64 t, %1; cvt.u32.u64 %0, t; }"
        : "=r"(r) : "l"(p));
    return r;
}

#define CP_ASYNC16(dst, src) \
    asm volatile("cp.async.cg.shared.global [%0], [%1], 16;" \
                 :: "r"(dst), "l"(src) : "memory")
#define CP_COMMIT()  asm volatile("cp.async.commit_group;" ::: "memory")
#define CP_WAIT0()   asm volatile("cp.async.wait_group 0;" ::: "memory")

#define LDSM4(R, addr) \
    asm volatile("ldmatrix.sync.aligned.m8n8.x4.shared.b16 {%0,%1,%2,%3}, [%4];" \
        : "=r"((R)[0]), "=r"((R)[1]), "=r"((R)[2]), "=r"((R)[3]) : "r"(addr))

#define MMA_BF16(ACC, A, B) \
    asm volatile("mma.sync.aligned.m16n8k16.row.col.f32.bf16.bf16.f32 " \
        "{%0,%1,%2,%3}, {%4,%5,%6,%7}, {%8,%9}, {%0,%1,%2,%3};" \
        : "+f"((ACC)[0]), "+f"((ACC)[1]), "+f"((ACC)[2]), "+f"((ACC)[3]) \
        : "r"((A)[0]), "r"((A)[1]), "r"((A)[2]), "r"((A)[3]), \
          "r"((B)[0]), "r"((B)[1]))

// ===========================================================================
// bf16-split MMA GEMM: C[M,N] = (Ahi+Alo)[M,K] @ (Bhi+Blo)[N,K]^T  (fp32 out)
// CTA tile 128x128, BK=32, 8 warps (2m x 4n), warp tile 64x32.
// smem row stride = 40 bf16 (80 B): ldmatrix 8-row phases hit banks
// (20*r mod 32) = {0,20,8,28,16,4,24,12} -> conflict-free.
// Double-buffered K-slabs via cp.async.
// ===========================================================================
__global__ __launch_bounds__(256) void gemm_mma(
    const __nv_bfloat16* __restrict__ Ahi, const __nv_bfloat16* __restrict__ Alo,
    const __nv_bfloat16* __restrict__ Bhi, const __nv_bfloat16* __restrict__ Blo,
    float* __restrict__ C, int M, int N, int K)
{
    extern __shared__ char smdyn[];
    const uint32_t sbase = smem_u32(smdyn);
    const int tid  = threadIdx.x;
    const int warp = tid >> 5;
    const int lane = tid & 31;
    const int wm = warp >> 2;            // 0..1  (m)
    const int wn = warp & 3;             // 0..3  (n)
    const int row0 = blockIdx.y * 128;
    const int col0 = blockIdx.x * 128;

    // tiles per stage: Ahi@0, Alo@10240, Bhi@20480, Blo@30720 (stride 40960)
    const __nv_bfloat16* gsrc[4] = {
        Ahi + (size_t)row0 * K, Alo + (size_t)row0 * K,
        Bhi + (size_t)col0 * K, Blo + (size_t)col0 * K };

    float acc[4][4][4];
#pragma unroll
    for (int a = 0; a < 4; a++)
#pragma unroll
        for (int b = 0; b < 4; b++)
#pragma unroll
            for (int c = 0; c < 4; c++) acc[a][b][c] = 0.0f;

    const int S = K >> 5;

    // prologue: stage 0
    {
        const int k0 = 0;
#pragma unroll
        for (int i = 0; i < 8; i++) {
            int c = tid + (i << 8);
            int op = c >> 9, cc = c & 511;
            int row = cc >> 2, kc = cc & 3;
            uint32_t dst = sbase + (uint32_t)(op * 10240 + row * 80 + kc * 16);
            const char* src = (const char*)(gsrc[op] + (size_t)row * K + k0) + kc * 16;
            CP_ASYNC16(dst, src);
        }
        CP_COMMIT();
        CP_WAIT0();
        __syncthreads();
    }

    for (int s = 0; s < S; s++) {
        const int st = s & 1;
        if (s + 1 < S) {
            const int k0 = (s + 1) << 5;
            const uint32_t stoff = (uint32_t)((st ^ 1) * 40960);
#pragma unroll
            for (int i = 0; i < 8; i++) {
                int c = tid + (i << 8);
                int op = c >> 9, cc = c & 511;
                int row = cc >> 2, kc = cc & 3;
                uint32_t dst = sbase + stoff + (uint32_t)(op * 10240 + row * 80 + kc * 16);
                const char* src = (const char*)(gsrc[op] + (size_t)row * K + k0) + kc * 16;
                CP_ASYNC16(dst, src);
            }
            CP_COMMIT();
        }

        const uint32_t base = sbase + (uint32_t)(st * 40960);
#pragma unroll
        for (int t = 0; t < 2; t++) {
            uint32_t ahi[4][4], alo[4][4], bhi[4][2], blo[4][2];
#pragma unroll
            for (int mf = 0; mf < 4; mf++) {
                int r = wm * 64 + mf * 16 + (lane & 15);
                uint32_t ad = base + (uint32_t)(r * 80 + t * 32 + ((lane >> 4) << 4));
                LDSM4(ahi[mf], ad);
                LDSM4(alo[mf], ad + 10240);
            }
#pragma unroll
            for (int g = 0; g < 2; g++) {
                int n = wn * 32 + g * 16 + (lane & 15);
                uint32_t bd = base + 20480u + (uint32_t)(n * 80 + t * 32 + ((lane >> 4) << 4));
                uint32_t h4[4], l4[4];
                LDSM4(h4, bd);
                LDSM4(l4, bd + 10240);
                bhi[2 * g][0]     = h4[0]; bhi[2 * g][1]     = h4[2];
                bhi[2 * g + 1][0] = h4[1]; bhi[2 * g + 1][1] = h4[3];
                blo[2 * g][0]     = l4[0]; blo[2 * g][1]     = l4[2];
                blo[2 * g + 1][0] = l4[1]; blo[2 * g + 1][1] = l4[3];
            }
#pragma unroll
            for (int mf = 0; mf < 4; mf++)
#pragma unroll
                for (int nf = 0; nf < 4; nf++) {
                    MMA_BF16(acc[mf][nf], ahi[mf], bhi[nf]);
                    MMA_BF16(acc[mf][nf], ahi[mf], blo[nf]);
                    MMA_BF16(acc[mf][nf], alo[mf], bhi[nf]);
                }
        }
        CP_WAIT0();
        __syncthreads();
    }

    // epilogue
    const int qr = lane >> 2;
    const int qc = (lane & 3) * 2;
#pragma unroll
    for (int mf = 0; mf < 4; mf++)
#pragma unroll
        for (int nf = 0; nf < 4; nf++) {
            int r = row0 + wm * 64 + mf * 16 + qr;
            int cI = col0 + wn * 32 + nf * 8 + qc;
            float2 v0 = make_float2(acc[mf][nf][0], acc[mf][nf][1]);
            float2 v1 = make_float2(acc[mf][nf][2], acc[mf][nf][3]);
            *(float2*)(C + (size_t)r * N + cI)       = v0;
            *(float2*)(C + (size_t)(r + 8) * N + cI) = v1;
        }
}

// ===========================================================================
// bf16 split conversion (layout preserved): v = hi + lo
// ===========================================================================
__global__ void split_kernel(const float* __restrict__ src,
                             __nv_bfloat16* __restrict__ hi,
                             __nv_bfloat16* __restrict__ lo, int n4)
{
    int i = blockIdx.x * blockDim.x + threadIdx.x;
    if (i >= n4) return;
    float4 v = *(const float4*)(src + (size_t)i * 4);
    float f[4] = {v.x, v.y, v.z, v.w};
    __nv_bfloat16 h[4], l[4];
#pragma unroll
    for (int j = 0; j < 4; j++) {
        h[j] = __float2bfloat16(f[j]);
        l[j] = __float2bfloat16(f[j] - __bfloat162float(h[j]));
    }
    *(__nv_bfloat162*)(hi + (size_t)i * 4)     = __nv_bfloat162(h[0], h[1]);
    *(__nv_bfloat162*)(hi + (size_t)i * 4 + 2) = __nv_bfloat162(h[2], h[3]);
    *(__nv_bfloat162*)(lo + (size_t)i * 4)     = __nv_bfloat162(l[0], l[1]);
    *(__nv_bfloat162*)(lo + (size_t)i * 4 + 2) = __nv_bfloat162(l[2], l[3]);
}

// Transposing split: W fp32 [K][N] -> hi/lo bf16 [N][K]
__global__ void splitT_kernel(const float* __restrict__ W,
                              __nv_bfloat16* __restrict__ hi,
                              __nv_bfloat16* __restrict__ lo, int K, int N)
{
    __shared__ float t[32][33];
    const int n0 = blockIdx.x * 32;
    const int k0 = blockIdx.y * 32;
    const int tx = threadIdx.x, ty = threadIdx.y;   // 32 x 8
#pragma unroll
    for (int j = 0; j < 4; j++)
        t[ty + j * 8][tx] = W[(size_t)(k0 + ty + j * 8) * N + n0 + tx];
    __syncthreads();
#pragma unroll
    for (int j = 0; j < 4; j++) {
        float v = t[tx][ty + j * 8];
        __nv_bfloat16 h = __float2bfloat16(v);
        __nv_bfloat16 l = __float2bfloat16(v - __bfloat162float(h));
        size_t o = (size_t)(n0 + ty + j * 8) * K + k0 + tx;
        hi[o] = h;
        lo[o] = l;
    }
}

// ===========================================================================
// RoPE tables: fp32 angle, exact double range-reduction, fast sincos on
// reduced arg (|r|<=pi, where __sincosf is accurate).
// ===========================================================================
__global__ void rope_table_kernel()
{
    int idx = blockIdx.x * blockDim.x + threadIdx.x;
    if (idx >= LSEQ * 128) return;
    int i = idx & 127;
    int l = idx >> 7;
    double ex   = (double)(2 * i) / 256.0;
    float  pf   = (float)pow(10000.0, ex);
    float  invf = __fdiv_rn(1.0f, pf);
    float  ang  = (float)l * invf;                 // fp32, as in jnp.outer
    double a  = (double)ang;
    double kq = rint(a * 0.15915494309189535);
    double r  = fma(-kq, 6.283185307179586, a);
    float  s, c;
    __sincosf((float)r, &s, &c);
    g_cos[idx] = c;
    g_sin[idx] = s;
}

__global__ void rope_apply_kernel(float* __restrict__ buf, int nheads)
{
    int l = blockIdx.x;
    int i = threadIdx.x;
    float c = g_cos[(size_t)l * 128 + i];
    float s = g_sin[(size_t)l * 128 + i];
    for (int h = 0; h < nheads; h++) {
        size_t base = (size_t)l * nheads * DH + (size_t)h * DH;
        float x1 = buf[base + i];
        float x2 = buf[base + i + 128];
        buf[base + i]       = x1 * c - x2 * s;
        buf[base + i + 128] = x2 * c + x1 * s;
    }
}

// ===========================================================================
// V mean over all 4096 keys (q<2048 rows attend uniformly — masking analysis)
// ===========================================================================
__global__ void vmean_kernel()
{
    int idx = blockIdx.x * blockDim.x + threadIdx.x;
    if (idx >= KDIM) return;
    double s = 0.0;
    for (int l = 0; l < LSEQ; l++)
        s += (double)g_v[(size_t)l * KDIM + idx];
    g_vmean[idx] = (float)(s * (1.0 / 4096.0));
}

__global__ void lowq_fill_kernel()
{
    int idx = blockIdx.x * blockDim.x + threadIdx.x;
    if (idx >= WIN * QDIM) return;
    int col = idx & (QDIM - 1);
    int h = col >> 8;
    int d = col & 255;
    g_att[idx] = g_vmean[(h >> 1) * 256 + d];
}

// ===========================================================================
// Accurate 50*tanh(x/50) via expm1f (no fast-math substitution).
// ===========================================================================
__device__ __forceinline__ float softcap50(float s)
{
    float x = __fdiv_rn(s * SCALEF, 50.0f);
    x = fminf(fmaxf(x, -15.0f), 15.0f);
    float e = expm1f(2.0f * x);
    return 50.0f * __fdiv_rn(e, e + 2.0f);
}

// ===========================================================================
// Flash attention, q >= 2048 only (softmax over k in [2048, q]); skipped
// columns contribute exactly 0.0f (fp32 masking analysis).
// ===========================================================================
__global__ __launch_bounds__(256) void flash_kernel()
{
    extern __shared__ float sm[];
    float* QsT = sm;
    float* KsT = QsT + 256 * 33;
    float* Vs  = KsT + 256 * 33;
    float* Ss  = Vs + 32 * 260;
    float* m_s = Ss + 32 * 33;
    float* l_s = m_s + 32;
    float* c_s = l_s + 32;

    const int tid = threadIdx.x;
    const int h   = blockIdx.y;
    const int hkv = h >> 1;
    const int q0  = WIN + (63 - (int)blockIdx.x) * 32;
    const int ty = tid >> 4, tx = tid & 15;
    const int r0 = 2 * ty, r1 = r0 + 1;

    for (int i = tid; i < 32 * 64; i += 256) {
        int r = i >> 6, c4 = i & 63;
        float4 v4 = *(const float4*)(g_q + (size_t)(q0 + r) * QDIM + h * DH + c4 * 4);
        int d = c4 * 4;
        QsT[(d + 0) * 33 + r] = v4.x;
        QsT[(d + 1) * 33 + r] = v4.y;
        QsT[(d + 2) * 33 + r] = v4.z;
        QsT[(d + 3) * 33 + r] = v4.w;
    }
    if (tid < 32) { m_s[tid] = -INFINITY; l_s[tid] = 0.0f; }
    float acc0[16], acc1[16];
#pragma unroll
    for (int c = 0; c < 16; c++) { acc0[c] = 0.0f; acc1[c] = 0.0f; }

    const int kend = q0 + 32;
    for (int k0 = WIN; k0 < kend; k0 += 32) {
        __syncthreads();
        for (int i = tid; i < 32 * 64; i += 256) {
            int r = i >> 6, c4 = i & 63;
            size_t gb = (size_t)(k0 + r) * KDIM + hkv * DH + c4 * 4;
            float4 kv = *(const float4*)(g_k + gb);
            int d = c4 * 4;
            KsT[(d + 0) * 33 + r] = kv.x;
            KsT[(d + 1) * 33 + r] = kv.y;
            KsT[(d + 2) * 33 + r] = kv.z;
            KsT[(d + 3) * 33 + r] = kv.w;
            float4 vv = *(const float4*)(g_v + gb);
            *(float4*)(Vs + r * 260 + c4 * 4) = vv;
        }
        __syncthreads();

        float s00 = 0.f, s01 = 0.f, s10 = 0.f, s11 = 0.f;
#pragma unroll 8
        for (int d = 0; d < 256; d++) {
            float a0 = QsT[d * 33 + r0];
            float a1 = QsT[d * 33 + r1];
            float b0 = KsT[d * 33 + tx];
            float b1 = KsT[d * 33 + tx + 16];
            s00 = fmaf(a0, b0, s00);
            s01 = fmaf(a0, b1, s01);
            s10 = fmaf(a1, b0, s10);
            s11 = fmaf(a1, b1, s11);
        }
        float t00 = softcap50(s00);
        float t01 = softcap50(s01);
        float t10 = softcap50(s10);
        float t11 = softcap50(s11);

        float a00 = (k0 + tx      > q0 + r0) ? NEGC : t00;
        float a01 = (k0 + tx + 16 > q0 + r0) ? NEGC : t01;
        float a10 = (k0 + tx      > q0 + r1) ? NEGC : t10;
        float a11 = (k0 + tx + 16 > q0 + r1) ? NEGC : t11;

        Ss[r0 * 33 + tx]      = a00;
        Ss[r0 * 33 + tx + 16] = a01;
        Ss[r1 * 33 + tx]      = a10;
        Ss[r1 * 33 + tx + 16] = a11;
        __syncthreads();

        if (tid < 32) {
            float* row = Ss + tid * 33;
            float mo = m_s[tid];
            float mx = mo;
#pragma unroll
            for (int j = 0; j < 32; j++) mx = fmaxf(mx, row[j]);
            float corr = expf(mo - mx);
            float l = l_s[tid] * corr;
#pragma unroll
            for (int j = 0; j < 32; j++) {
                float pv = expf(row[j] - mx);
                row[j] = pv;
                l += pv;
            }
            m_s[tid] = mx;
            l_s[tid] = l;
            c_s[tid] = corr;
        }
        __syncthreads();

        float cr0 = c_s[r0], cr1 = c_s[r1];
#pragma unroll
        for (int c = 0; c < 16; c++) { acc0[c] *= cr0; acc1[c] *= cr1; }
        const float* pr0 = Ss + r0 * 33;
        const float* pr1 = Ss + r1 * 33;
        for (int j = 0; j < 32; j++) {
            float p0 = pr0[j], p1 = pr1[j];
            const float* vr = Vs + j * 260 + tx;
#pragma unroll
            for (int c = 0; c < 16; c++) {
                float vv = vr[16 * c];
                acc0[c] = fmaf(p0, vv, acc0[c]);
                acc1[c] = fmaf(p1, vv, acc1[c]);
            }
        }
    }

    float li0 = l_s[r0], li1 = l_s[r1];
    size_t ob0 = (size_t)(q0 + r0) * QDIM + h * DH + tx;
    size_t ob1 = (size_t)(q0 + r1) * QDIM + h * DH + tx;
#pragma unroll
    for (int c = 0; c < 16; c++) {
        g_att[ob0 + 16 * c] = __fdiv_rn(acc0[c], li0);
        g_att[ob1 + 16 * c] = __fdiv_rn(acc1[c], li1);
    }
}

// ===========================================================================
extern "C" void kernel_launch(void* const* d_in, const int* in_sizes, int n_in,
                              void* d_out, int out_size)
{
    const float* x  = (const float*)d_in[0];
    const float* wq = (const float*)d_in[2];
    const float* wk = (const float*)d_in[3];
    const float* wv = (const float*)d_in[4];
    const float* wo = (const float*)d_in[5];
    float* out = (float*)d_out;

    float *pq, *pk, *pv, *patt;
    cudaGetSymbolAddress((void**)&pq,   g_q);
    cudaGetSymbolAddress((void**)&pk,   g_k);
    cudaGetSymbolAddress((void**)&pv,   g_v);
    cudaGetSymbolAddress((void**)&patt, g_att);
    __nv_bfloat16 *xhi, *xlo, *ahi, *alo;
    __nv_bfloat16 *qhi, *qlo, *khi, *klo, *vhi, *vlo, *ohi, *olo;
    cudaGetSymbolAddress((void**)&xhi, g_xhi);
    cudaGetSymbolAddress((void**)&xlo, g_xlo);
    cudaGetSymbolAddress((void**)&ahi, g_ahi);
    cudaGetSymbolAddress((void**)&alo, g_alo);
    cudaGetSymbolAddress((void**)&qhi, g_wqhi);
    cudaGetSymbolAddress((void**)&qlo, g_wqlo);
    cudaGetSymbolAddress((void**)&khi, g_wkhi);
    cudaGetSymbolAddress((void**)&klo, g_wklo);
    cudaGetSymbolAddress((void**)&vhi, g_wvhi);
    cudaGetSymbolAddress((void**)&vlo, g_wvlo);
    cudaGetSymbolAddress((void**)&ohi, g_wohi);
    cudaGetSymbolAddress((void**)&olo, g_wolo);

    dim3 blk(256);
    const int GEMM_SMEM = 81920;   // 4 tiles x 10240 B x 2 stages
    cudaFuncSetAttribute(gemm_mma, cudaFuncAttributeMaxDynamicSharedMemorySize, GEMM_SMEM);

    // Split inputs to bf16 hi/lo
    {
        int n4 = LSEQ * HID / 4;
        split_kernel<<<(n4 + 255) / 256, blk>>>(x, xhi, xlo, n4);
        dim3 tb(32, 8);
        splitT_kernel<<<dim3(QDIM / 32, HID / 32), tb>>>(wq, qhi, qlo, HID, QDIM);
        splitT_kernel<<<dim3(KDIM / 32, HID / 32), tb>>>(wk, khi, klo, HID, KDIM);
        splitT_kernel<<<dim3(KDIM / 32, HID / 32), tb>>>(wv, vhi, vlo, HID, KDIM);
        splitT_kernel<<<dim3(HID / 32, QDIM / 32), tb>>>(wo, ohi, olo, QDIM, HID);
    }

    // QKV projections on tensor cores (mma.sync HMMA path)
    gemm_mma<<<dim3(QDIM / 128, LSEQ / 128), blk, GEMM_SMEM>>>(xhi, xlo, qhi, qlo, pq, LSEQ, QDIM, HID);
    gemm_mma<<<dim3(KDIM / 128, LSEQ / 128), blk, GEMM_SMEM>>>(xhi, xlo, khi, klo, pk, LSEQ, KDIM, HID);
    gemm_mma<<<dim3(KDIM / 128, LSEQ / 128), blk, GEMM_SMEM>>>(xhi, xlo, vhi, vlo, pv, LSEQ, KDIM, HID);

    // RoPE
    rope_table_kernel<<<(LSEQ * 128 + 255) / 256, blk>>>();
    rope_apply_kernel<<<LSEQ, 128>>>(pq, NHQ);
    rope_apply_kernel<<<LSEQ, 128>>>(pk, NKV);

    // lowq rows = V mean
    vmean_kernel<<<(KDIM + 255) / 256, blk>>>();
    lowq_fill_kernel<<<(WIN * QDIM + 255) / 256, blk>>>();

    // Flash attention (q >= 2048)
    const int FLASH_SMEM = (256 * 33 * 2 + 32 * 260 + 32 * 33 + 96) * 4;
    cudaFuncSetAttribute(flash_kernel,
                         cudaFuncAttributeMaxDynamicSharedMemorySize, FLASH_SMEM);
    flash_kernel<<<dim3(64, NHQ), blk, FLASH_SMEM>>>();

    // Output projection on tensor cores
    {
        int n4 = LSEQ * QDIM / 4;
        split_kernel<<<(n4 + 255) / 256, blk>>>(patt, ahi, alo, n4);
    }
    gemm_mma<<<dim3(HID / 128, LSEQ / 128), blk, GEMM_SMEM>>>(ahi, alo, ohi, olo, out, LSEQ, HID, QDIM);
}

// round 8
// speedup vs baseline: 2.4159x; 1.1298x over previous
#include <cuda_runtime.h>
#include <cuda_bf16.h>
#include <math.h>
#include <stdint.h>

#define LSEQ 4096
#define NHQ 8
#define NKV 4
#define DH 256
#define HID 2304
#define WIN 2048
#define QDIM (NHQ*DH)   /* 2048 */
#define KDIM (NKV*DH)   /* 1024 */

#define SCALEF 0.05892556509887896f   /* 288^-0.5 */
#define NEGC  (-1.0e9f)

// fp32 intermediates
static __device__ float g_q[(size_t)LSEQ * QDIM];
static __device__ float g_k[(size_t)LSEQ * KDIM];
static __device__ float g_v[(size_t)LSEQ * KDIM];
static __device__ float g_att[(size_t)LSEQ * QDIM];
static __device__ float g_vmean[KDIM];
static __device__ float g_lowrow[HID];
static __device__ float g_cos[(size_t)LSEQ * 128];
static __device__ float g_sin[(size_t)LSEQ * 128];

// bf16-split operands
static __device__ __nv_bfloat16 g_xhi[(size_t)LSEQ * HID];
static __device__ __nv_bfloat16 g_xlo[(size_t)LSEQ * HID];
static __device__ __nv_bfloat16 g_ahi[(size_t)WIN * QDIM];
static __device__ __nv_bfloat16 g_alo[(size_t)WIN * QDIM];
// weights transposed to [N][K] K-major
static __device__ __nv_bfloat16 g_wqhi[(size_t)QDIM * HID];
static __device__ __nv_bfloat16 g_wqlo[(size_t)QDIM * HID];
static __device__ __nv_bfloat16 g_wkhi[(size_t)KDIM * HID];
static __device__ __nv_bfloat16 g_wklo[(size_t)KDIM * HID];
static __device__ __nv_bfloat16 g_wvhi[(size_t)KDIM * HID];
static __device__ __nv_bfloat16 g_wvlo[(size_t)KDIM * HID];
static __device__ __nv_bfloat16 g_wohi[(size_t)HID * QDIM];
static __device__ __nv_bfloat16 g_wolo[(size_t)HID * QDIM];

// ===========================================================================
// Helpers (base-target PTX only: ldmatrix / mma.sync / cp.async)
// ===========================================================================
__device__ __forceinline__ uint32_t smem_u32(const void* p) {
    uint32_t r;
    asm("{ .reg .u64 t; cvta.to.shared.u64 t, %1; cvt.u32.u64 %0, t; }"
        : "=r"(r) : "l"(p));
    return r;
}

#define CP_ASYNC16(dst, src) \
    asm volatile("cp.async.cg.shared.global [%0], [%1], 16;" \
                 :: "r"(dst), "l"(src) : "memory")
#define CP_COMMIT()  asm volatile("cp.async.commit_group;" ::: "memory")
#define CP_WAIT0()   asm volatile("cp.async.wait_group 0;" ::: "memory")

#define LDSM4(R, addr) \
    asm volatile("ldmatrix.sync.aligned.m8n8.x4.shared.b16 {%0,%1,%2,%3}, [%4];" \
        : "=r"((R)[0]), "=r"((R)[1]), "=r"((R)[2]), "=r"((R)[3]) : "r"(addr))

#define MMA_BF16(ACC, A, B) \
    asm volatile("mma.sync.aligned.m16n8k16.row.col.f32.bf16.bf16.f32 " \
        "{%0,%1,%2,%3}, {%4,%5,%6,%7}, {%8,%9}, {%0,%1,%2,%3};" \
        : "+f"((ACC)[0]), "+f"((ACC)[1]), "+f"((ACC)[2]), "+f"((ACC)[3]) \
        : "r"((A)[0]), "r"((A)[1]), "r"((A)[2]), "r"((A)[3]), \
          "r"((B)[0]), "r"((B)[1]))

// ===========================================================================
// bf16-split MMA GEMM: C[M,N] = (Ahi+Alo)[M,K] @ (Bhi+Blo)[N,K]^T  (fp32 out)
// CTA tile 128x128, BK=32, 8 warps (2m x 4n). smem row stride 80 B
// (conflict-free ldmatrix). Double-buffered K-slabs via cp.async.
// ===========================================================================
__global__ __launch_bounds__(256) void gemm_mma(
    const __nv_bfloat16* __restrict__ Ahi, const __nv_bfloat16* __restrict__ Alo,
    const __nv_bfloat16* __restrict__ Bhi, const __nv_bfloat16* __restrict__ Blo,
    float* __restrict__ C, int M, int N, int K)
{
    extern __shared__ char smdyn[];
    const uint32_t sbase = smem_u32(smdyn);
    const int tid  = threadIdx.x;
    const int warp = tid >> 5;
    const int lane = tid & 31;
    const int wm = warp >> 2;
    const int wn = warp & 3;
    const int row0 = blockIdx.y * 128;
    const int col0 = blockIdx.x * 128;

    const __nv_bfloat16* gsrc[4] = {
        Ahi + (size_t)row0 * K, Alo + (size_t)row0 * K,
        Bhi + (size_t)col0 * K, Blo + (size_t)col0 * K };

    float acc[4][4][4];
#pragma unroll
    for (int a = 0; a < 4; a++)
#pragma unroll
        for (int b = 0; b < 4; b++)
#pragma unroll
            for (int c = 0; c < 4; c++) acc[a][b][c] = 0.0f;

    const int S = K >> 5;

    {
#pragma unroll
        for (int i = 0; i < 8; i++) {
            int c = tid + (i << 8);
            int op = c >> 9, cc = c & 511;
            int row = cc >> 2, kc = cc & 3;
            uint32_t dst = sbase + (uint32_t)(op * 10240 + row * 80 + kc * 16);
            const char* src = (const char*)(gsrc[op] + (size_t)row * K) + kc * 16;
            CP_ASYNC16(dst, src);
        }
        CP_COMMIT();
        CP_WAIT0();
        __syncthreads();
    }

    for (int s = 0; s < S; s++) {
        const int st = s & 1;
        if (s + 1 < S) {
            const int k0 = (s + 1) << 5;
            const uint32_t stoff = (uint32_t)((st ^ 1) * 40960);
#pragma unroll
            for (int i = 0; i < 8; i++) {
                int c = tid + (i << 8);
                int op = c >> 9, cc = c & 511;
                int row = cc >> 2, kc = cc & 3;
                uint32_t dst = sbase + stoff + (uint32_t)(op * 10240 + row * 80 + kc * 16);
                const char* src = (const char*)(gsrc[op] + (size_t)row * K + k0) + kc * 16;
                CP_ASYNC16(dst, src);
            }
            CP_COMMIT();
        }

        const uint32_t base = sbase + (uint32_t)(st * 40960);
#pragma unroll
        for (int t = 0; t < 2; t++) {
            uint32_t ahi[4][4], alo[4][4], bhi[4][2], blo[4][2];
#pragma unroll
            for (int mf = 0; mf < 4; mf++) {
                int r = wm * 64 + mf * 16 + (lane & 15);
                uint32_t ad = base + (uint32_t)(r * 80 + t * 32 + ((lane >> 4) << 4));
                LDSM4(ahi[mf], ad);
                LDSM4(alo[mf], ad + 10240);
            }
#pragma unroll
            for (int g = 0; g < 2; g++) {
                int n = wn * 32 + g * 16 + (lane & 15);
                uint32_t bd = base + 20480u + (uint32_t)(n * 80 + t * 32 + ((lane >> 4) << 4));
                uint32_t h4[4], l4[4];
                LDSM4(h4, bd);
                LDSM4(l4, bd + 10240);
                bhi[2 * g][0]     = h4[0]; bhi[2 * g][1]     = h4[2];
                bhi[2 * g + 1][0] = h4[1]; bhi[2 * g + 1][1] = h4[3];
                blo[2 * g][0]     = l4[0]; blo[2 * g][1]     = l4[2];
                blo[2 * g + 1][0] = l4[1]; blo[2 * g + 1][1] = l4[3];
            }
#pragma unroll
            for (int mf = 0; mf < 4; mf++)
#pragma unroll
                for (int nf = 0; nf < 4; nf++) {
                    MMA_BF16(acc[mf][nf], ahi[mf], bhi[nf]);
                    MMA_BF16(acc[mf][nf], ahi[mf], blo[nf]);
                    MMA_BF16(acc[mf][nf], alo[mf], bhi[nf]);
                }
        }
        CP_WAIT0();
        __syncthreads();
    }

    const int qr = lane >> 2;
    const int qc = (lane & 3) * 2;
#pragma unroll
    for (int mf = 0; mf < 4; mf++)
#pragma unroll
        for (int nf = 0; nf < 4; nf++) {
            int r = row0 + wm * 64 + mf * 16 + qr;
            int cI = col0 + wn * 32 + nf * 8 + qc;
            float2 v0 = make_float2(acc[mf][nf][0], acc[mf][nf][1]);
            float2 v1 = make_float2(acc[mf][nf][2], acc[mf][nf][3]);
            *(float2*)(C + (size_t)r * N + cI)       = v0;
            *(float2*)(C + (size_t)(r + 8) * N + cI) = v1;
        }
}

// ===========================================================================
// bf16 split conversion (layout preserved): v = hi + lo
// ===========================================================================
__global__ void split_kernel(const float* __restrict__ src,
                             __nv_bfloat16* __restrict__ hi,
                             __nv_bfloat16* __restrict__ lo, int n4)
{
    int i = blockIdx.x * blockDim.x + threadIdx.x;
    if (i >= n4) return;
    float4 v = *(const float4*)(src + (size_t)i * 4);
    float f[4] = {v.x, v.y, v.z, v.w};
    __nv_bfloat16 h[4], l[4];
#pragma unroll
    for (int j = 0; j < 4; j++) {
        h[j] = __float2bfloat16(f[j]);
        l[j] = __float2bfloat16(f[j] - __bfloat162float(h[j]));
    }
    *(__nv_bfloat162*)(hi + (size_t)i * 4)     = __nv_bfloat162(h[0], h[1]);
    *(__nv_bfloat162*)(hi + (size_t)i * 4 + 2) = __nv_bfloat162(h[2], h[3]);
    *(__nv_bfloat162*)(lo + (size_t)i * 4)     = __nv_bfloat162(l[0], l[1]);
    *(__nv_bfloat162*)(lo + (size_t)i * 4 + 2) = __nv_bfloat162(l[2], l[3]);
}

// Transposing split: W fp32 [K][N] -> hi/lo bf16 [N][K]
__global__ void splitT_kernel(const float* __restrict__ W,
                              __nv_bfloat16* __restrict__ hi,
                              __nv_bfloat16* __restrict__ lo, int K, int N)
{
    __shared__ float t[32][33];
    const int n0 = blockIdx.x * 32;
    const int k0 = blockIdx.y * 32;
    const int tx = threadIdx.x, ty = threadIdx.y;   // 32 x 8
#pragma unroll
    for (int j = 0; j < 4; j++)
        t[ty + j * 8][tx] = W[(size_t)(k0 + ty + j * 8) * N + n0 + tx];
    __syncthreads();
#pragma unroll
    for (int j = 0; j < 4; j++) {
        float v = t[tx][ty + j * 8];
        __nv_bfloat16 h = __float2bfloat16(v);
        __nv_bfloat16 l = __float2bfloat16(v - __bfloat162float(h));
        size_t o = (size_t)(n0 + ty + j * 8) * K + k0 + tx;
        hi[o] = h;
        lo[o] = l;
    }
}

// ===========================================================================
// RoPE tables for l >= WIN only (lowq rows never need rope).
// fp32 angle, exact double range-reduction, fast sincos on |r|<=pi.
// ===========================================================================
__global__ void rope_table_kernel()
{
    int idx = blockIdx.x * blockDim.x + threadIdx.x;
    if (idx >= WIN * 128) return;
    int i = idx & 127;
    int l = WIN + (idx >> 7);
    double ex   = (double)(2 * i) / 256.0;
    float  pf   = (float)pow(10000.0, ex);
    float  invf = __fdiv_rn(1.0f, pf);
    float  ang  = (float)l * invf;                 // fp32, as in jnp.outer
    double a  = (double)ang;
    double kq = rint(a * 0.15915494309189535);
    double r  = fma(-kq, 6.283185307179586, a);
    float  s, c;
    __sincosf((float)r, &s, &c);
    g_cos[(size_t)l * 128 + i] = c;
    g_sin[(size_t)l * 128 + i] = s;
}

__global__ void rope_apply_kernel(float* __restrict__ buf, int nheads)
{
    int l = WIN + blockIdx.x;      // only rows >= WIN are ever consumed
    int i = threadIdx.x;
    float c = g_cos[(size_t)l * 128 + i];
    float s = g_sin[(size_t)l * 128 + i];
    for (int h = 0; h < nheads; h++) {
        size_t base = (size_t)l * nheads * DH + (size_t)h * DH;
        float x1 = buf[base + i];
        float x2 = buf[base + i + 128];
        buf[base + i]       = x1 * c - x2 * s;
        buf[base + i + 128] = x2 * c + x1 * s;
    }
}

// ===========================================================================
// V mean over all 4096 keys (q<2048 rows attend uniformly — masking analysis)
// ===========================================================================
__global__ void vmean_kernel()
{
    int idx = blockIdx.x * blockDim.x + threadIdx.x;
    if (idx >= KDIM) return;
    double s = 0.0;
    for (int l = 0; l < LSEQ; l++)
        s += (double)g_v[(size_t)l * KDIM + idx];
    g_vmean[idx] = (float)(s * (1.0 / 4096.0));
}

// Low-row output GEMV: lowrow[j] = sum_i r[i] * wo[i][j], where r is the
// (identical) lowq attention row: r[h*256+d] = vmean[(h/2)*256+d].
__global__ void lowout_kernel(const float* __restrict__ wo)
{
    int j = blockIdx.x * blockDim.x + threadIdx.x;
    if (j >= HID) return;
    float s = 0.0f;
    for (int i = 0; i < QDIM; i++) {
        int h = i >> 8, d = i & 255;
        float r = g_vmean[(h >> 1) * 256 + d];
        s = fmaf(r, wo[(size_t)i * HID + j], s);
    }
    g_lowrow[j] = s;
}

// Broadcast the low row into out[0..WIN)
__global__ void lowfill_kernel(float* __restrict__ out)
{
    int idx = blockIdx.x * blockDim.x + threadIdx.x;
    if (idx >= WIN * HID) return;
    out[idx] = g_lowrow[idx % HID];
}

// ===========================================================================
// Accurate 50*tanh(x/50) via expm1f (no fast-math substitution).
// ===========================================================================
__device__ __forceinline__ float softcap50(float s)
{
    float x = __fdiv_rn(s * SCALEF, 50.0f);
    x = fminf(fmaxf(x, -15.0f), 15.0f);
    float e = expm1f(2.0f * x);
    return 50.0f * __fdiv_rn(e, e + 2.0f);
}

// ===========================================================================
// Flash attention, q >= 2048 only (softmax over k in [2048, q]); skipped
// columns contribute exactly 0.0f (fp32 masking analysis).
// ===========================================================================
__global__ __launch_bounds__(256) void flash_kernel()
{
    extern __shared__ float sm[];
    float* QsT = sm;
    float* KsT = QsT + 256 * 33;
    float* Vs  = KsT + 256 * 33;
    float* Ss  = Vs + 32 * 260;
    float* m_s = Ss + 32 * 33;
    float* l_s = m_s + 32;
    float* c_s = l_s + 32;

    const int tid = threadIdx.x;
    const int h   = blockIdx.y;
    const int hkv = h >> 1;
    const int q0  = WIN + (63 - (int)blockIdx.x) * 32;
    const int ty = tid >> 4, tx = tid & 15;
    const int r0 = 2 * ty, r1 = r0 + 1;

    for (int i = tid; i < 32 * 64; i += 256) {
        int r = i >> 6, c4 = i & 63;
        float4 v4 = *(const float4*)(g_q + (size_t)(q0 + r) * QDIM + h * DH + c4 * 4);
        int d = c4 * 4;
        QsT[(d + 0) * 33 + r] = v4.x;
        QsT[(d + 1) * 33 + r] = v4.y;
        QsT[(d + 2) * 33 + r] = v4.z;
        QsT[(d + 3) * 33 + r] = v4.w;
    }
    if (tid < 32) { m_s[tid] = -INFINITY; l_s[tid] = 0.0f; }
    float acc0[16], acc1[16];
#pragma unroll
    for (int c = 0; c < 16; c++) { acc0[c] = 0.0f; acc1[c] = 0.0f; }

    const int kend = q0 + 32;
    for (int k0 = WIN; k0 < kend; k0 += 32) {
        __syncthreads();
        for (int i = tid; i < 32 * 64; i += 256) {
            int r = i >> 6, c4 = i & 63;
            size_t gb = (size_t)(k0 + r) * KDIM + hkv * DH + c4 * 4;
            float4 kv = *(const float4*)(g_k + gb);
            int d = c4 * 4;
            KsT[(d + 0) * 33 + r] = kv.x;
            KsT[(d + 1) * 33 + r] = kv.y;
            KsT[(d + 2) * 33 + r] = kv.z;
            KsT[(d + 3) * 33 + r] = kv.w;
            float4 vv = *(const float4*)(g_v + gb);
            *(float4*)(Vs + r * 260 + c4 * 4) = vv;
        }
        __syncthreads();

        float s00 = 0.f, s01 = 0.f, s10 = 0.f, s11 = 0.f;
#pragma unroll 8
        for (int d = 0; d < 256; d++) {
            float a0 = QsT[d * 33 + r0];
            float a1 = QsT[d * 33 + r1];
            float b0 = KsT[d * 33 + tx];
            float b1 = KsT[d * 33 + tx + 16];
            s00 = fmaf(a0, b0, s00);
            s01 = fmaf(a0, b1, s01);
            s10 = fmaf(a1, b0, s10);
            s11 = fmaf(a1, b1, s11);
        }
        float t00 = softcap50(s00);
        float t01 = softcap50(s01);
        float t10 = softcap50(s10);
        float t11 = softcap50(s11);

        float a00 = (k0 + tx      > q0 + r0) ? NEGC : t00;
        float a01 = (k0 + tx + 16 > q0 + r0) ? NEGC : t01;
        float a10 = (k0 + tx      > q0 + r1) ? NEGC : t10;
        float a11 = (k0 + tx + 16 > q0 + r1) ? NEGC : t11;

        Ss[r0 * 33 + tx]      = a00;
        Ss[r0 * 33 + tx + 16] = a01;
        Ss[r1 * 33 + tx]      = a10;
        Ss[r1 * 33 + tx + 16] = a11;
        __syncthreads();

        if (tid < 32) {
            float* row = Ss + tid * 33;
            float mo = m_s[tid];
            float mx = mo;
#pragma unroll
            for (int j = 0; j < 32; j++) mx = fmaxf(mx, row[j]);
            float corr = expf(mo - mx);
            float l = l_s[tid] * corr;
#pragma unroll
            for (int j = 0; j < 32; j++) {
                float pv = expf(row[j] - mx);
                row[j] = pv;
                l += pv;
            }
            m_s[tid] = mx;
            l_s[tid] = l;
            c_s[tid] = corr;
        }
        __syncthreads();

        float cr0 = c_s[r0], cr1 = c_s[r1];
#pragma unroll
        for (int c = 0; c < 16; c++) { acc0[c] *= cr0; acc1[c] *= cr1; }
        const float* pr0 = Ss + r0 * 33;
        const float* pr1 = Ss + r1 * 33;
        for (int j = 0; j < 32; j++) {
            float p0 = pr0[j], p1 = pr1[j];
            const float* vr = Vs + j * 260 + tx;
#pragma unroll
            for (int c = 0; c < 16; c++) {
                float vv = vr[16 * c];
                acc0[c] = fmaf(p0, vv, acc0[c]);
                acc1[c] = fmaf(p1, vv, acc1[c]);
            }
        }
    }

    float li0 = l_s[r0], li1 = l_s[r1];
    size_t ob0 = (size_t)(q0 + r0) * QDIM + h * DH + tx;
    size_t ob1 = (size_t)(q0 + r1) * QDIM + h * DH + tx;
#pragma unroll
    for (int c = 0; c < 16; c++) {
        g_att[ob0 + 16 * c] = __fdiv_rn(acc0[c], li0);
        g_att[ob1 + 16 * c] = __fdiv_rn(acc1[c], li1);
    }
}

// ===========================================================================
extern "C" void kernel_launch(void* const* d_in, const int* in_sizes, int n_in,
                              void* d_out, int out_size)
{
    const float* x  = (const float*)d_in[0];
    const float* wq = (const float*)d_in[2];
    const float* wk = (const float*)d_in[3];
    const float* wv = (const float*)d_in[4];
    const float* wo = (const float*)d_in[5];
    float* out = (float*)d_out;

    float *pq, *pk, *pv, *patt;
    cudaGetSymbolAddress((void**)&pq,   g_q);
    cudaGetSymbolAddress((void**)&pk,   g_k);
    cudaGetSymbolAddress((void**)&pv,   g_v);
    cudaGetSymbolAddress((void**)&patt, g_att);
    __nv_bfloat16 *xhi, *xlo, *ahi, *alo;
    __nv_bfloat16 *qhi, *qlo, *khi, *klo, *vhi, *vlo, *ohi, *olo;
    cudaGetSymbolAddress((void**)&xhi, g_xhi);
    cudaGetSymbolAddress((void**)&xlo, g_xlo);
    cudaGetSymbolAddress((void**)&ahi, g_ahi);
    cudaGetSymbolAddress((void**)&alo, g_alo);
    cudaGetSymbolAddress((void**)&qhi, g_wqhi);
    cudaGetSymbolAddress((void**)&qlo, g_wqlo);
    cudaGetSymbolAddress((void**)&khi, g_wkhi);
    cudaGetSymbolAddress((void**)&klo, g_wklo);
    cudaGetSymbolAddress((void**)&vhi, g_wvhi);
    cudaGetSymbolAddress((void**)&vlo, g_wvlo);
    cudaGetSymbolAddress((void**)&ohi, g_wohi);
    cudaGetSymbolAddress((void**)&olo, g_wolo);

    dim3 blk(256);
    const int GEMM_SMEM = 81920;
    cudaFuncSetAttribute(gemm_mma, cudaFuncAttributeMaxDynamicSharedMemorySize, GEMM_SMEM);

    // Split inputs to bf16 hi/lo
    {
        int n4 = LSEQ * HID / 4;
        split_kernel<<<(n4 + 255) / 256, blk>>>(x, xhi, xlo, n4);
        dim3 tb(32, 8);
        splitT_kernel<<<dim3(QDIM / 32, HID / 32), tb>>>(wq, qhi, qlo, HID, QDIM);
        splitT_kernel<<<dim3(KDIM / 32, HID / 32), tb>>>(wk, khi, klo, HID, KDIM);
        splitT_kernel<<<dim3(KDIM / 32, HID / 32), tb>>>(wv, vhi, vlo, HID, KDIM);
        splitT_kernel<<<dim3(HID / 32, QDIM / 32), tb>>>(wo, ohi, olo, QDIM, HID);
    }

    // Projections (dead-row-pruned): Q,K only rows >= WIN; V full.
    gemm_mma<<<dim3(QDIM / 128, WIN / 128), blk, GEMM_SMEM>>>(
        xhi + (size_t)WIN * HID, xlo + (size_t)WIN * HID, qhi, qlo,
        pq + (size_t)WIN * QDIM, WIN, QDIM, HID);
    gemm_mma<<<dim3(KDIM / 128, WIN / 128), blk, GEMM_SMEM>>>(
        xhi + (size_t)WIN * HID, xlo + (size_t)WIN * HID, khi, klo,
        pk + (size_t)WIN * KDIM, WIN, KDIM, HID);
    gemm_mma<<<dim3(KDIM / 128, LSEQ / 128), blk, GEMM_SMEM>>>(
        xhi, xlo, vhi, vlo, pv, LSEQ, KDIM, HID);

    // RoPE (rows >= WIN only)
    rope_table_kernel<<<(WIN * 128 + 255) / 256, blk>>>();
    rope_apply_kernel<<<WIN, 128>>>(pq, NHQ);
    rope_apply_kernel<<<WIN, 128>>>(pk, NKV);

    // lowq output rows: V mean -> GEMV -> broadcast into out[0..WIN)
    vmean_kernel<<<(KDIM + 255) / 256, blk>>>();
    lowout_kernel<<<(HID + 255) / 256, blk>>>(wo);
    lowfill_kernel<<<(WIN * HID + 255) / 256, blk>>>(out);

    // Flash attention (q >= 2048)
    const int FLASH_SMEM = (256 * 33 * 2 + 32 * 260 + 32 * 33 + 96) * 4;
    cudaFuncSetAttribute(flash_kernel,
                         cudaFuncAttributeMaxDynamicSharedMemorySize, FLASH_SMEM);
    flash_kernel<<<dim3(64, NHQ), blk, FLASH_SMEM>>>();

    // Output projection: high rows only
    {
        int n4 = WIN * QDIM / 4;
        split_kernel<<<(n4 + 255) / 256, blk>>>(patt + (size_t)WIN * QDIM, ahi, alo, n4);
    }
    gemm_mma<<<dim3(HID / 128, WIN / 128), blk, GEMM_SMEM>>>(
        ahi, alo, ohi, olo, out + (size_t)WIN * HID, WIN, HID, QDIM);
}

// round 9
// speedup vs baseline: 3.2961x; 1.3643x over previous
#include <cuda_runtime.h>
#include <cuda_bf16.h>
#include <math.h>
#include <stdint.h>

#define LSEQ 4096
#define NHQ 8
#define NKV 4
#define DH 256
#define HID 2304
#define WIN 2048
#define QDIM (NHQ*DH)   /* 2048 */
#define KDIM (NKV*DH)   /* 1024 */

#define SCALEF 0.05892556509887896f   /* 288^-0.5 */
#define NEGC  (-1.0e9f)

// fp32 intermediates
static __device__ float g_q[(size_t)LSEQ * QDIM];
static __device__ float g_k[(size_t)LSEQ * KDIM];
static __device__ float g_v[(size_t)LSEQ * KDIM];
static __device__ float g_vmean[KDIM];
static __device__ float g_lowrow[HID];
static __device__ float g_cos[(size_t)LSEQ * 128];
static __device__ float g_sin[(size_t)LSEQ * 128];

// bf16-split operands
static __device__ __nv_bfloat16 g_xhi[(size_t)LSEQ * HID];
static __device__ __nv_bfloat16 g_xlo[(size_t)LSEQ * HID];
static __device__ __nv_bfloat16 g_ahi[(size_t)WIN * QDIM];
static __device__ __nv_bfloat16 g_alo[(size_t)WIN * QDIM];
// roped, compacted (rows = l - WIN)
static __device__ __nv_bfloat16 g_qhi[(size_t)WIN * QDIM];
static __device__ __nv_bfloat16 g_qlo[(size_t)WIN * QDIM];
static __device__ __nv_bfloat16 g_khi[(size_t)WIN * KDIM];
static __device__ __nv_bfloat16 g_klo[(size_t)WIN * KDIM];
// V transposed per kv head: [hkv][d=256][k=2048]  (rows = d, cols = k - WIN)
static __device__ __nv_bfloat16 g_vthi[(size_t)NKV * DH * WIN];
static __device__ __nv_bfloat16 g_vtlo[(size_t)NKV * DH * WIN];
// weights transposed to [N][K] K-major
static __device__ __nv_bfloat16 g_wqhi[(size_t)QDIM * HID];
static __device__ __nv_bfloat16 g_wqlo[(size_t)QDIM * HID];
static __device__ __nv_bfloat16 g_wkhi[(size_t)KDIM * HID];
static __device__ __nv_bfloat16 g_wklo[(size_t)KDIM * HID];
static __device__ __nv_bfloat16 g_wvhi[(size_t)KDIM * HID];
static __device__ __nv_bfloat16 g_wvlo[(size_t)KDIM * HID];
static __device__ __nv_bfloat16 g_wohi[(size_t)HID * QDIM];
static __device__ __nv_bfloat16 g_wolo[(size_t)HID * QDIM];

// ===========================================================================
// Helpers (base-target PTX only: ldmatrix / mma.sync / cp.async)
// ===========================================================================
__device__ __forceinline__ uint32_t smem_u32(const void* p) {
    uint32_t r;
    asm("{ .reg .u64 t; cvta.to.shared.u64 t, %1; cvt.u32.u64 %0, t; }"
        : "=r"(r) : "l"(p));
    return r;
}

#define CP_ASYNC16(dst, src) \
    asm volatile("cp.async.cg.shared.global [%0], [%1], 16;" \
                 :: "r"(dst), "l"(src) : "memory")
#define CP_COMMIT()  asm volatile("cp.async.commit_group;" ::: "memory")
#define CP_WAIT0()   asm volatile("cp.async.wait_group 0;" ::: "memory")

#define LDSM4(R, addr) \
    asm volatile("ldmatrix.sync.aligned.m8n8.x4.shared.b16 {%0,%1,%2,%3}, [%4];" \
        : "=r"((R)[0]), "=r"((R)[1]), "=r"((R)[2]), "=r"((R)[3]) : "r"(addr))

#define MMA_BF16(ACC, A, B) \
    asm volatile("mma.sync.aligned.m16n8k16.row.col.f32.bf16.bf16.f32 " \
        "{%0,%1,%2,%3}, {%4,%5,%6,%7}, {%8,%9}, {%0,%1,%2,%3};" \
        : "+f"((ACC)[0]), "+f"((ACC)[1]), "+f"((ACC)[2]), "+f"((ACC)[3]) \
        : "r"((A)[0]), "r"((A)[1]), "r"((A)[2]), "r"((A)[3]), \
          "r"((B)[0]), "r"((B)[1]))

// ===========================================================================
// bf16-split MMA GEMM (unchanged from R7/R8 — validated)
// ===========================================================================
__global__ __launch_bounds__(256) void gemm_mma(
    const __nv_bfloat16* __restrict__ Ahi, const __nv_bfloat16* __restrict__ Alo,
    const __nv_bfloat16* __restrict__ Bhi, const __nv_bfloat16* __restrict__ Blo,
    float* __restrict__ C, int M, int N, int K)
{
    extern __shared__ char smdyn[];
    const uint32_t sbase = smem_u32(smdyn);
    const int tid  = threadIdx.x;
    const int warp = tid >> 5;
    const int lane = tid & 31;
    const int wm = warp >> 2;
    const int wn = warp & 3;
    const int row0 = blockIdx.y * 128;
    const int col0 = blockIdx.x * 128;

    const __nv_bfloat16* gsrc[4] = {
        Ahi + (size_t)row0 * K, Alo + (size_t)row0 * K,
        Bhi + (size_t)col0 * K, Blo + (size_t)col0 * K };

    float acc[4][4][4];
#pragma unroll
    for (int a = 0; a < 4; a++)
#pragma unroll
        for (int b = 0; b < 4; b++)
#pragma unroll
            for (int c = 0; c < 4; c++) acc[a][b][c] = 0.0f;

    const int S = K >> 5;

    {
#pragma unroll
        for (int i = 0; i < 8; i++) {
            int c = tid + (i << 8);
            int op = c >> 9, cc = c & 511;
            int row = cc >> 2, kc = cc & 3;
            uint32_t dst = sbase + (uint32_t)(op * 10240 + row * 80 + kc * 16);
            const char* src = (const char*)(gsrc[op] + (size_t)row * K) + kc * 16;
            CP_ASYNC16(dst, src);
        }
        CP_COMMIT();
        CP_WAIT0();
        __syncthreads();
    }

    for (int s = 0; s < S; s++) {
        const int st = s & 1;
        if (s + 1 < S) {
            const int k0 = (s + 1) << 5;
            const uint32_t stoff = (uint32_t)((st ^ 1) * 40960);
#pragma unroll
            for (int i = 0; i < 8; i++) {
                int c = tid + (i << 8);
                int op = c >> 9, cc = c & 511;
                int row = cc >> 2, kc = cc & 3;
                uint32_t dst = sbase + stoff + (uint32_t)(op * 10240 + row * 80 + kc * 16);
                const char* src = (const char*)(gsrc[op] + (size_t)row * K + k0) + kc * 16;
                CP_ASYNC16(dst, src);
            }
            CP_COMMIT();
        }

        const uint32_t base = sbase + (uint32_t)(st * 40960);
#pragma unroll
        for (int t = 0; t < 2; t++) {
            uint32_t ahi[4][4], alo[4][4], bhi[4][2], blo[4][2];
#pragma unroll
            for (int mf = 0; mf < 4; mf++) {
                int r = wm * 64 + mf * 16 + (lane & 15);
                uint32_t ad = base + (uint32_t)(r * 80 + t * 32 + ((lane >> 4) << 4));
                LDSM4(ahi[mf], ad);
                LDSM4(alo[mf], ad + 10240);
            }
#pragma unroll
            for (int g = 0; g < 2; g++) {
                int n = wn * 32 + g * 16 + (lane & 15);
                uint32_t bd = base + 20480u + (uint32_t)(n * 80 + t * 32 + ((lane >> 4) << 4));
                uint32_t h4[4], l4[4];
                LDSM4(h4, bd);
                LDSM4(l4, bd + 10240);
                bhi[2 * g][0]     = h4[0]; bhi[2 * g][1]     = h4[2];
                bhi[2 * g + 1][0] = h4[1]; bhi[2 * g + 1][1] = h4[3];
                blo[2 * g][0]     = l4[0]; blo[2 * g][1]     = l4[2];
                blo[2 * g + 1][0] = l4[1]; blo[2 * g + 1][1] = l4[3];
            }
#pragma unroll
            for (int mf = 0; mf < 4; mf++)
#pragma unroll
                for (int nf = 0; nf < 4; nf++) {
                    MMA_BF16(acc[mf][nf], ahi[mf], bhi[nf]);
                    MMA_BF16(acc[mf][nf], ahi[mf], blo[nf]);
                    MMA_BF16(acc[mf][nf], alo[mf], bhi[nf]);
                }
        }
        CP_WAIT0();
        __syncthreads();
    }

    const int qr = lane >> 2;
    const int qc = (lane & 3) * 2;
#pragma unroll
    for (int mf = 0; mf < 4; mf++)
#pragma unroll
        for (int nf = 0; nf < 4; nf++) {
            int r = row0 + wm * 64 + mf * 16 + qr;
            int cI = col0 + wn * 32 + nf * 8 + qc;
            float2 v0 = make_float2(acc[mf][nf][0], acc[mf][nf][1]);
            float2 v1 = make_float2(acc[mf][nf][2], acc[mf][nf][3]);
            *(float2*)(C + (size_t)r * N + cI)       = v0;
            *(float2*)(C + (size_t)(r + 8) * N + cI) = v1;
        }
}

// ===========================================================================
// bf16 split conversion (layout preserved)
// ===========================================================================
__global__ void split_kernel(const float* __restrict__ src,
                             __nv_bfloat16* __restrict__ hi,
                             __nv_bfloat16* __restrict__ lo, int n4)
{
    int i = blockIdx.x * blockDim.x + threadIdx.x;
    if (i >= n4) return;
    float4 v = *(const float4*)(src + (size_t)i * 4);
    float f[4] = {v.x, v.y, v.z, v.w};
    __nv_bfloat16 h[4], l[4];
#pragma unroll
    for (int j = 0; j < 4; j++) {
        h[j] = __float2bfloat16(f[j]);
        l[j] = __float2bfloat16(f[j] - __bfloat162float(h[j]));
    }
    *(__nv_bfloat162*)(hi + (size_t)i * 4)     = __nv_bfloat162(h[0], h[1]);
    *(__nv_bfloat162*)(hi + (size_t)i * 4 + 2) = __nv_bfloat162(h[2], h[3]);
    *(__nv_bfloat162*)(lo + (size_t)i * 4)     = __nv_bfloat162(l[0], l[1]);
    *(__nv_bfloat162*)(lo + (size_t)i * 4 + 2) = __nv_bfloat162(l[2], l[3]);
}

// Transposing split: W fp32 [K][N] -> hi/lo bf16 [N][K]
__global__ void splitT_kernel(const float* __restrict__ W,
                              __nv_bfloat16* __restrict__ hi,
                              __nv_bfloat16* __restrict__ lo, int K, int N)
{
    __shared__ float t[32][33];
    const int n0 = blockIdx.x * 32;
    const int k0 = blockIdx.y * 32;
    const int tx = threadIdx.x, ty = threadIdx.y;
#pragma unroll
    for (int j = 0; j < 4; j++)
        t[ty + j * 8][tx] = W[(size_t)(k0 + ty + j * 8) * N + n0 + tx];
    __syncthreads();
#pragma unroll
    for (int j = 0; j < 4; j++) {
        float v = t[tx][ty + j * 8];
        __nv_bfloat16 h = __float2bfloat16(v);
        __nv_bfloat16 l = __float2bfloat16(v - __bfloat162float(h));
        size_t o = (size_t)(n0 + ty + j * 8) * K + k0 + tx;
        hi[o] = h;
        lo[o] = l;
    }
}

// ===========================================================================
// RoPE tables for l >= WIN (double range-reduction; fast sincos on |r|<=pi)
// ===========================================================================
__global__ void rope_table_kernel()
{
    int idx = blockIdx.x * blockDim.x + threadIdx.x;
    if (idx >= WIN * 128) return;
    int i = idx & 127;
    int l = WIN + (idx >> 7);
    double ex   = (double)(2 * i) / 256.0;
    float  pf   = (float)pow(10000.0, ex);
    float  invf = __fdiv_rn(1.0f, pf);
    float  ang  = (float)l * invf;
    double a  = (double)ang;
    double kq = rint(a * 0.15915494309189535);
    double r  = fma(-kq, 6.283185307179586, a);
    float  s, c;
    __sincosf((float)r, &s, &c);
    g_cos[(size_t)l * 128 + i] = c;
    g_sin[(size_t)l * 128 + i] = s;
}

// RoPE + bf16 hi/lo split, compacted to rows (l - WIN).
__global__ void rope_split_kernel(const float* __restrict__ buf, int nheads,
                                  __nv_bfloat16* __restrict__ hi,
                                  __nv_bfloat16* __restrict__ lo)
{
    int l = WIN + blockIdx.x;
    int i = threadIdx.x;        // 0..127
    float c = g_cos[(size_t)l * 128 + i];
    float s = g_sin[(size_t)l * 128 + i];
    int nd = nheads * DH;
    for (int h = 0; h < nheads; h++) {
        size_t base = (size_t)l * nd + (size_t)h * DH;
        float x1 = buf[base + i];
        float x2 = buf[base + i + 128];
        float y1 = x1 * c - x2 * s;
        float y2 = x2 * c + x1 * s;
        size_t o = (size_t)(l - WIN) * nd + (size_t)h * DH;
        __nv_bfloat16 h1 = __float2bfloat16(y1);
        __nv_bfloat16 h2 = __float2bfloat16(y2);
        hi[o + i]       = h1;
        hi[o + i + 128] = h2;
        lo[o + i]       = __float2bfloat16(y1 - __bfloat162float(h1));
        lo[o + i + 128] = __float2bfloat16(y2 - __bfloat162float(h2));
    }
}

// V transpose-split: g_v rows >= WIN -> Vt[hkv][d][k-WIN] bf16 hi/lo.
__global__ void vt_split_kernel()
{
    __shared__ float t[32][33];
    const int k0  = blockIdx.x * 32;       // relative key
    const int d0  = blockIdx.y * 32;
    const int hkv = blockIdx.z;
    const int tx = threadIdx.x, ty = threadIdx.y;   // 32 x 8
#pragma unroll
    for (int j = 0; j < 4; j++)
        t[ty + j * 8][tx] = g_v[(size_t)(WIN + k0 + ty + j * 8) * KDIM + hkv * DH + d0 + tx];
    __syncthreads();
#pragma unroll
    for (int j = 0; j < 4; j++) {
        float v = t[tx][ty + j * 8];        // (k=tx, d=ty+j*8)
        __nv_bfloat16 h = __float2bfloat16(v);
        __nv_bfloat16 l = __float2bfloat16(v - __bfloat162float(h));
        size_t o = (size_t)hkv * DH * WIN + (size_t)(d0 + ty + j * 8) * WIN + k0 + tx;
        g_vthi[o] = h;
        g_vtlo[o] = l;
    }
}

// ===========================================================================
// V mean + low-row output (unchanged; lowq rows attend uniformly)
// ===========================================================================
__global__ void vmean_kernel()
{
    int idx = blockIdx.x * blockDim.x + threadIdx.x;
    if (idx >= KDIM) return;
    double s = 0.0;
    for (int l = 0; l < LSEQ; l++)
        s += (double)g_v[(size_t)l * KDIM + idx];
    g_vmean[idx] = (float)(s * (1.0 / 4096.0));
}

__global__ void lowout_kernel(const float* __restrict__ wo)
{
    int j = blockIdx.x * blockDim.x + threadIdx.x;
    if (j >= HID) return;
    float s = 0.0f;
    for (int i = 0; i < QDIM; i++) {
        int h = i >> 8, d = i & 255;
        float r = g_vmean[(h >> 1) * 256 + d];
        s = fmaf(r, wo[(size_t)i * HID + j], s);
    }
    g_lowrow[j] = s;
}

__global__ void lowfill_kernel(float* __restrict__ out)
{
    int idx = blockIdx.x * blockDim.x + threadIdx.x;
    if (idx >= WIN * HID) return;
    out[idx] = g_lowrow[idx % HID];
}

// ===========================================================================
// Accurate 50*tanh(x/50) via expm1f
// ===========================================================================
__device__ __forceinline__ float softcap50(float s)
{
    float x = __fdiv_rn(s * SCALEF, 50.0f);
    x = fminf(fmaxf(x, -15.0f), 15.0f);
    float e = expm1f(2.0f * x);
    return 50.0f * __fdiv_rn(e, e + 2.0f);
}

// ===========================================================================
// Tensor-core flash attention (q >= 2048). Block = 64 queries x 1 head,
// k-tiles of 32. QK^T and PV via 3-term bf16-split mma.sync; row softmax.
// Output written directly as bf16 hi/lo into g_ahi/g_alo (rows q - WIN).
// SMEM map (bytes):
//   QHI 0        (64x528=33792)     QLO 33792
//   KHI 67584    (32x528=16896)     KLO 84480
//   VTHI 101376  (256x80=20480)     VTLO 121856
//   SS  142336   (64x36x4=9216)
//   PHI 151552   (64x80=5120)       PLO 156672
//   M 161792  L 162048  CC 162304   total 162560
// ===========================================================================
__global__ __launch_bounds__(256) void flash_mma(
    const __nv_bfloat16* __restrict__ Qhi, const __nv_bfloat16* __restrict__ Qlo,
    const __nv_bfloat16* __restrict__ Khi, const __nv_bfloat16* __restrict__ Klo,
    const __nv_bfloat16* __restrict__ Vthi, const __nv_bfloat16* __restrict__ Vtlo,
    __nv_bfloat16* __restrict__ Ohi, __nv_bfloat16* __restrict__ Olo)
{
    extern __shared__ char dsm[];
    const uint32_t sb = smem_u32(dsm);
    float* SS  = (float*)(dsm + 142336);
    float* m_s = (float*)(dsm + 161792);
    float* l_s = (float*)(dsm + 162048);
    float* c_s = (float*)(dsm + 162304);

    const int tid  = threadIdx.x;
    const int warp = tid >> 5;
    const int lane = tid & 31;
    const int h    = blockIdx.y;
    const int hkv  = h >> 1;
    const int it   = 31 - (int)blockIdx.x;     // descending work
    const int q0r  = it * 64;                  // relative q (q - WIN)
    const int nk   = 2 * it + 2;               // k-tiles of 32

    // Load Q tile (hi+lo), 64 rows x 512 B each
#pragma unroll
    for (int i = 0; i < 16; i++) {
        int c = tid + (i << 8);                // 0..4095
        int op = c >> 11, cc = c & 2047;
        int row = cc >> 5, ch = cc & 31;
        uint32_t dst = sb + (uint32_t)(op * 33792 + row * 528 + ch * 16);
        const char* src = (const char*)((op ? Qlo : Qhi)
                          + (size_t)(q0r + row) * QDIM + h * DH) + ch * 16;
        CP_ASYNC16(dst, src);
    }
    CP_COMMIT();
    if (tid < 64) { m_s[tid] = -INFINITY; l_s[tid] = 0.0f; }

    float o[4][4][4];
#pragma unroll
    for (int a = 0; a < 4; a++)
#pragma unroll
        for (int b = 0; b < 4; b++)
#pragma unroll
            for (int c = 0; c < 4; c++) o[a][b][c] = 0.0f;

    CP_WAIT0();
    __syncthreads();

    const int wm = warp >> 1;      // 0..3 (16 q rows each)
    const int wn = warp & 1;       // 0..1 (16 k cols each)

    for (int t = 0; t < nk; t++) {
        const int k0r = t * 32;
        // load K (32x512B hi/lo) and VT (256x64B hi/lo)
#pragma unroll
        for (int i = 0; i < 8; i++) {
            int c = tid + (i << 8);            // 0..2047
            int op = c >> 10, cc = c & 1023;
            int row = cc >> 5, ch = cc & 31;
            uint32_t dst = sb + 67584u + (uint32_t)(op * 16896 + row * 528 + ch * 16);
            const char* src = (const char*)((op ? Klo : Khi)
                              + (size_t)(k0r + row) * KDIM + hkv * DH) + ch * 16;
            CP_ASYNC16(dst, src);
        }
#pragma unroll
        for (int i = 0; i < 8; i++) {
            int c = tid + (i << 8);
            int op = c >> 10, cc = c & 1023;
            int row = cc >> 2, ch = cc & 3;
            uint32_t dst = sb + 101376u + (uint32_t)(op * 20480 + row * 80 + ch * 16);
            const char* src = (const char*)((op ? Vtlo : Vthi)
                              + (size_t)hkv * DH * WIN + (size_t)row * WIN + k0r) + ch * 16;
            CP_ASYNC16(dst, src);
        }
        CP_COMMIT();
        CP_WAIT0();
        __syncthreads();

        // ---- QK^T: warp tile 16q x 16k over d=256 ----
        float s[2][4];
#pragma unroll
        for (int nf = 0; nf < 2; nf++)
#pragma unroll
            for (int e = 0; e < 4; e++) s[nf][e] = 0.0f;

#pragma unroll
        for (int ds = 0; ds < 16; ds++) {
            uint32_t ah[4], al[4], kh4[4], kl4[4];
            uint32_t qa = sb + (uint32_t)((wm * 16 + (lane & 15)) * 528
                           + ds * 32 + ((lane >> 4) << 4));
            LDSM4(ah, qa);
            LDSM4(al, qa + 33792);
            uint32_t ka = sb + 67584u + (uint32_t)((wn * 16 + (lane & 15)) * 528
                           + ds * 32 + ((lane >> 4) << 4));
            LDSM4(kh4, ka);
            LDSM4(kl4, ka + 16896);
            uint32_t bh0[2] = {kh4[0], kh4[2]}, bh1[2] = {kh4[1], kh4[3]};
            uint32_t bl0[2] = {kl4[0], kl4[2]}, bl1[2] = {kl4[1], kl4[3]};
            MMA_BF16(s[0], ah, bh0); MMA_BF16(s[0], ah, bl0); MMA_BF16(s[0], al, bh0);
            MMA_BF16(s[1], ah, bh1); MMA_BF16(s[1], ah, bl1); MMA_BF16(s[1], al, bh1);
        }

        // softcap + causal mask + store to SS
        const int qr = lane >> 2, qc = (lane & 3) * 2;
#pragma unroll
        for (int nf = 0; nf < 2; nf++)
#pragma unroll
            for (int e = 0; e < 4; e++) {
                int r = wm * 16 + qr + ((e >> 1) * 8);
                int cI = wn * 16 + nf * 8 + qc + (e & 1);
                float v = softcap50(s[nf][e]);
                if (k0r + cI > q0r + r) v = NEGC;
                SS[r * 36 + cI] = v;
            }
        __syncthreads();

        // ---- row softmax (64 threads) + split P to bf16 hi/lo ----
        if (tid < 64) {
            float* rp = SS + tid * 36;
            __nv_bfloat16* ph = (__nv_bfloat16*)(dsm + 151552) + tid * 40;
            __nv_bfloat16* pl = (__nv_bfloat16*)(dsm + 156672) + tid * 40;
            float mo = m_s[tid];
            float mx = mo;
#pragma unroll
            for (int j = 0; j < 32; j++) mx = fmaxf(mx, rp[j]);
            float corr = expf(mo - mx);
            float l = l_s[tid] * corr;
#pragma unroll
            for (int j = 0; j < 32; j++) {
                float p = expf(rp[j] - mx);
                l += p;
                __nv_bfloat16 hh = __float2bfloat16(p);
                ph[j] = hh;
                pl[j] = __float2bfloat16(p - __bfloat162float(hh));
            }
            m_s[tid] = mx;
            l_s[tid] = l;
            c_s[tid] = corr;
        }
        __syncthreads();

        // ---- rescale O by corr ----
#pragma unroll
        for (int mf = 0; mf < 4; mf++) {
            float c0 = c_s[mf * 16 + qr];
            float c1 = c_s[mf * 16 + qr + 8];
#pragma unroll
            for (int nf = 0; nf < 4; nf++) {
                o[mf][nf][0] *= c0; o[mf][nf][1] *= c0;
                o[mf][nf][2] *= c1; o[mf][nf][3] *= c1;
            }
        }

        // ---- PV: warp owns d-slice 32 (warp*32); A=P[64x32], B=VT ----
#pragma unroll
        for (int ks = 0; ks < 2; ks++) {
            uint32_t aph[4][4], apl[4][4], bh[4][2], bl[4][2];
#pragma unroll
            for (int mf = 0; mf < 4; mf++) {
                uint32_t pa = sb + 151552u + (uint32_t)((mf * 16 + (lane & 15)) * 80
                               + ks * 32 + ((lane >> 4) << 4));
                LDSM4(aph[mf], pa);
                LDSM4(apl[mf], pa + 5120);
            }
#pragma unroll
            for (int g = 0; g < 2; g++) {
                uint32_t va = sb + 101376u + (uint32_t)((warp * 32 + g * 16 + (lane & 15)) * 80
                               + ks * 32 + ((lane >> 4) << 4));
                uint32_t vh4[4], vl4[4];
                LDSM4(vh4, va);
                LDSM4(vl4, va + 20480);
                bh[2 * g][0]     = vh4[0]; bh[2 * g][1]     = vh4[2];
                bh[2 * g + 1][0] = vh4[1]; bh[2 * g + 1][1] = vh4[3];
                bl[2 * g][0]     = vl4[0]; bl[2 * g][1]     = vl4[2];
                bl[2 * g + 1][0] = vl4[1]; bl[2 * g + 1][1] = vl4[3];
            }
#pragma unroll
            for (int mf = 0; mf < 4; mf++)
#pragma unroll
                for (int nf = 0; nf < 4; nf++) {
                    MMA_BF16(o[mf][nf], aph[mf], bh[nf]);
                    MMA_BF16(o[mf][nf], aph[mf], bl[nf]);
                    MMA_BF16(o[mf][nf], apl[mf], bh[nf]);
                }
        }
        __syncthreads();   // before next tile overwrites K/VT/P
    }

    // ---- epilogue: O/l -> bf16 hi/lo into g_ahi/g_alo ----
    const int qr = lane >> 2, qc = (lane & 3) * 2;
#pragma unroll
    for (int mf = 0; mf < 4; mf++) {
        float li0 = l_s[mf * 16 + qr];
        float li1 = l_s[mf * 16 + qr + 8];
        int r0 = q0r + mf * 16 + qr;
#pragma unroll
        for (int nf = 0; nf < 4; nf++) {
            int dcol = warp * 32 + nf * 8 + qc;
            size_t o0 = (size_t)r0 * QDIM + h * DH + dcol;
            size_t o1 = (size_t)(r0 + 8) * QDIM + h * DH + dcol;
            float v00 = __fdiv_rn(o[mf][nf][0], li0);
            float v01 = __fdiv_rn(o[mf][nf][1], li0);
            float v10 = __fdiv_rn(o[mf][nf][2], li1);
            float v11 = __fdiv_rn(o[mf][nf][3], li1);
            __nv_bfloat16 h00 = __float2bfloat16(v00), h01 = __float2bfloat16(v01);
            __nv_bfloat16 h10 = __float2bfloat16(v10), h11 = __float2bfloat16(v11);
            *(__nv_bfloat162*)(Ohi + o0) = __nv_bfloat162(h00, h01);
            *(__nv_bfloat162*)(Ohi + o1) = __nv_bfloat162(h10, h11);
            *(__nv_bfloat162*)(Olo + o0) = __nv_bfloat162(
                __float2bfloat16(v00 - __bfloat162float(h00)),
                __float2bfloat16(v01 - __bfloat162float(h01)));
            *(__nv_bfloat162*)(Olo + o1) = __nv_bfloat162(
                __float2bfloat16(v10 - __bfloat162float(h10)),
                __float2bfloat16(v11 - __bfloat162float(h11)));
        }
    }
}

// ===========================================================================
extern "C" void kernel_launch(void* const* d_in, const int* in_sizes, int n_in,
                              void* d_out, int out_size)
{
    const float* x  = (const float*)d_in[0];
    const float* wq = (const float*)d_in[2];
    const float* wk = (const float*)d_in[3];
    const float* wv = (const float*)d_in[4];
    const float* wo = (const float*)d_in[5];
    float* out = (float*)d_out;

    float *pq, *pk, *pv;
    cudaGetSymbolAddress((void**)&pq, g_q);
    cudaGetSymbolAddress((void**)&pk, g_k);
    cudaGetSymbolAddress((void**)&pv, g_v);
    __nv_bfloat16 *xhi, *xlo, *ahi, *alo, *qshi, *qslo, *kshi, *kslo, *vthi, *vtlo;
    __nv_bfloat16 *wqh, *wql, *wkh, *wkl, *wvh, *wvl, *woh, *wol;
    cudaGetSymbolAddress((void**)&xhi,  g_xhi);
    cudaGetSymbolAddress((void**)&xlo,  g_xlo);
    cudaGetSymbolAddress((void**)&ahi,  g_ahi);
    cudaGetSymbolAddress((void**)&alo,  g_alo);
    cudaGetSymbolAddress((void**)&qshi, g_qhi);
    cudaGetSymbolAddress((void**)&qslo, g_qlo);
    cudaGetSymbolAddress((void**)&kshi, g_khi);
    cudaGetSymbolAddress((void**)&kslo, g_klo);
    cudaGetSymbolAddress((void**)&vthi, g_vthi);
    cudaGetSymbolAddress((void**)&vtlo, g_vtlo);
    cudaGetSymbolAddress((void**)&wqh,  g_wqhi);
    cudaGetSymbolAddress((void**)&wql,  g_wqlo);
    cudaGetSymbolAddress((void**)&wkh,  g_wkhi);
    cudaGetSymbolAddress((void**)&wkl,  g_wklo);
    cudaGetSymbolAddress((void**)&wvh,  g_wvhi);
    cudaGetSymbolAddress((void**)&wvl,  g_wvlo);
    cudaGetSymbolAddress((void**)&woh,  g_wohi);
    cudaGetSymbolAddress((void**)&wol,  g_wolo);

    dim3 blk(256);
    const int GEMM_SMEM  = 81920;
    const int FLASH_SMEM = 162560;
    cudaFuncSetAttribute(gemm_mma, cudaFuncAttributeMaxDynamicSharedMemorySize, GEMM_SMEM);
    cudaFuncSetAttribute(flash_mma, cudaFuncAttributeMaxDynamicSharedMemorySize, FLASH_SMEM);

    // Split inputs to bf16 hi/lo
    {
        int n4 = LSEQ * HID / 4;
        split_kernel<<<(n4 + 255) / 256, blk>>>(x, xhi, xlo, n4);
        dim3 tb(32, 8);
        splitT_kernel<<<dim3(QDIM / 32, HID / 32), tb>>>(wq, wqh, wql, HID, QDIM);
        splitT_kernel<<<dim3(KDIM / 32, HID / 32), tb>>>(wk, wkh, wkl, HID, KDIM);
        splitT_kernel<<<dim3(KDIM / 32, HID / 32), tb>>>(wv, wvh, wvl, HID, KDIM);
        splitT_kernel<<<dim3(HID / 32, QDIM / 32), tb>>>(wo, woh, wol, QDIM, HID);
    }

    // Projections: Q,K rows >= WIN only; V full (vmean needs all rows)
    gemm_mma<<<dim3(QDIM / 128, WIN / 128), blk, GEMM_SMEM>>>(
        xhi + (size_t)WIN * HID, xlo + (size_t)WIN * HID, wqh, wql,
        pq + (size_t)WIN * QDIM, WIN, QDIM, HID);
    gemm_mma<<<dim3(KDIM / 128, WIN / 128), blk, GEMM_SMEM>>>(
        xhi + (size_t)WIN * HID, xlo + (size_t)WIN * HID, wkh, wkl,
        pk + (size_t)WIN * KDIM, WIN, KDIM, HID);
    gemm_mma<<<dim3(KDIM / 128, LSEQ / 128), blk, GEMM_SMEM>>>(
        xhi, xlo, wvh, wvl, pv, LSEQ, KDIM, HID);

    // RoPE tables + rope-split Q/K; V transpose-split
    rope_table_kernel<<<(WIN * 128 + 255) / 256, blk>>>();
    rope_split_kernel<<<WIN, 128>>>(pq, NHQ, qshi, qslo);
    rope_split_kernel<<<WIN, 128>>>(pk, NKV, kshi, kslo);
    {
        dim3 tb(32, 8);
        vt_split_kernel<<<dim3(WIN / 32, DH / 32, NKV), tb>>>();
    }

    // lowq output rows
    vmean_kernel<<<(KDIM + 255) / 256, blk>>>();
    lowout_kernel<<<(HID + 255) / 256, blk>>>(wo);
    lowfill_kernel<<<(WIN * HID + 255) / 256, blk>>>(out);

    // Tensor-core flash attention (q >= 2048); writes ahi/alo directly
    flash_mma<<<dim3(32, NHQ), blk, FLASH_SMEM>>>(
        qshi, qslo, kshi, kslo, vthi, vtlo, ahi, alo);

    // Output projection: high rows only
    gemm_mma<<<dim3(HID / 128, WIN / 128), blk, GEMM_SMEM>>>(
        ahi, alo, woh, wol, out + (size_t)WIN * HID, WIN, HID, QDIM);
}

// round 10
// speedup vs baseline: 5.7407x; 1.7417x over previous
#include <cuda_runtime.h>
#include <cuda_bf16.h>
#include <math.h>
#include <stdint.h>

#define LSEQ 4096
#define NHQ 8
#define NKV 4
#define DH 256
#define HID 2304
#define WIN 2048
#define QDIM (NHQ*DH)   /* 2048 */
#define KDIM (NKV*DH)   /* 1024 */

#define SCALEF 0.05892556509887896f   /* 288^-0.5 */
#define NEGC  (-1.0e9f)

// fp32 intermediates
static __device__ float g_q[(size_t)LSEQ * QDIM];
static __device__ float g_k[(size_t)LSEQ * KDIM];
static __device__ float g_v[(size_t)LSEQ * KDIM];
static __device__ float g_vmean[KDIM];
static __device__ float g_lowrow[HID];
static __device__ float g_invf[128];
static __device__ float g_xpart[16 * HID];
static __device__ float g_xsum[HID];
static __device__ float g_vpart[8 * KDIM];
static __device__ float g_lowpart[8 * HID];

// bf16-split operands
static __device__ __nv_bfloat16 g_xhi[(size_t)LSEQ * HID];
static __device__ __nv_bfloat16 g_xlo[(size_t)LSEQ * HID];
static __device__ __nv_bfloat16 g_ahi[(size_t)WIN * QDIM];
static __device__ __nv_bfloat16 g_alo[(size_t)WIN * QDIM];
// roped, compacted (rows = l - WIN)
static __device__ __nv_bfloat16 g_qhi[(size_t)WIN * QDIM];
static __device__ __nv_bfloat16 g_qlo[(size_t)WIN * QDIM];
static __device__ __nv_bfloat16 g_khi[(size_t)WIN * KDIM];
static __device__ __nv_bfloat16 g_klo[(size_t)WIN * KDIM];
// V transposed per kv head: [hkv][d=256][k-WIN=2048]
static __device__ __nv_bfloat16 g_vthi[(size_t)NKV * DH * WIN];
static __device__ __nv_bfloat16 g_vtlo[(size_t)NKV * DH * WIN];
// weights transposed to [N][K] K-major
static __device__ __nv_bfloat16 g_wqhi[(size_t)QDIM * HID];
static __device__ __nv_bfloat16 g_wqlo[(size_t)QDIM * HID];
static __device__ __nv_bfloat16 g_wkhi[(size_t)KDIM * HID];
static __device__ __nv_bfloat16 g_wklo[(size_t)KDIM * HID];
static __device__ __nv_bfloat16 g_wvhi[(size_t)KDIM * HID];
static __device__ __nv_bfloat16 g_wvlo[(size_t)KDIM * HID];
static __device__ __nv_bfloat16 g_wohi[(size_t)HID * QDIM];
static __device__ __nv_bfloat16 g_wolo[(size_t)HID * QDIM];

// ===========================================================================
// Helpers (base-target PTX only)
// ===========================================================================
__device__ __forceinline__ uint32_t smem_u32(const void* p) {
    uint32_t r;
    asm("{ .reg .u64 t; cvta.to.shared.u64 t, %1; cvt.u32.u64 %0, t; }"
        : "=r"(r) : "l"(p));
    return r;
}

#define CP_ASYNC16(dst, src) \
    asm volatile("cp.async.cg.shared.global [%0], [%1], 16;" \
                 :: "r"(dst), "l"(src) : "memory")
#define CP_COMMIT()  asm volatile("cp.async.commit_group;" ::: "memory")
#define CP_WAIT0()   asm volatile("cp.async.wait_group 0;" ::: "memory")
#define CP_WAIT1()   asm volatile("cp.async.wait_group 1;" ::: "memory")

#define LDSM4(R, addr) \
    asm volatile("ldmatrix.sync.aligned.m8n8.x4.shared.b16 {%0,%1,%2,%3}, [%4];" \
        : "=r"((R)[0]), "=r"((R)[1]), "=r"((R)[2]), "=r"((R)[3]) : "r"(addr))

#define MMA_BF16(ACC, A, B) \
    asm volatile("mma.sync.aligned.m16n8k16.row.col.f32.bf16.bf16.f32 " \
        "{%0,%1,%2,%3}, {%4,%5,%6,%7}, {%8,%9}, {%0,%1,%2,%3};" \
        : "+f"((ACC)[0]), "+f"((ACC)[1]), "+f"((ACC)[2]), "+f"((ACC)[3]) \
        : "r"((A)[0]), "r"((A)[1]), "r"((A)[2]), "r"((A)[3]), \
          "r"((B)[0]), "r"((B)[1]))

// ===========================================================================
// bf16-split MMA GEMM (validated R7-R9)
// ===========================================================================
__global__ __launch_bounds__(256) void gemm_mma(
    const __nv_bfloat16* __restrict__ Ahi, const __nv_bfloat16* __restrict__ Alo,
    const __nv_bfloat16* __restrict__ Bhi, const __nv_bfloat16* __restrict__ Blo,
    float* __restrict__ C, int M, int N, int K)
{
    extern __shared__ char smdyn[];
    const uint32_t sbase = smem_u32(smdyn);
    const int tid  = threadIdx.x;
    const int warp = tid >> 5;
    const int lane = tid & 31;
    const int wm = warp >> 2;
    const int wn = warp & 3;
    const int row0 = blockIdx.y * 128;
    const int col0 = blockIdx.x * 128;

    const __nv_bfloat16* gsrc[4] = {
        Ahi + (size_t)row0 * K, Alo + (size_t)row0 * K,
        Bhi + (size_t)col0 * K, Blo + (size_t)col0 * K };

    float acc[4][4][4];
#pragma unroll
    for (int a = 0; a < 4; a++)
#pragma unroll
        for (int b = 0; b < 4; b++)
#pragma unroll
            for (int c = 0; c < 4; c++) acc[a][b][c] = 0.0f;

    const int S = K >> 5;

    {
#pragma unroll
        for (int i = 0; i < 8; i++) {
            int c = tid + (i << 8);
            int op = c >> 9, cc = c & 511;
            int row = cc >> 2, kc = cc & 3;
            uint32_t dst = sbase + (uint32_t)(op * 10240 + row * 80 + kc * 16);
            const char* src = (const char*)(gsrc[op] + (size_t)row * K) + kc * 16;
            CP_ASYNC16(dst, src);
        }
        CP_COMMIT();
        CP_WAIT0();
        __syncthreads();
    }

    for (int s = 0; s < S; s++) {
        const int st = s & 1;
        if (s + 1 < S) {
            const int k0 = (s + 1) << 5;
            const uint32_t stoff = (uint32_t)((st ^ 1) * 40960);
#pragma unroll
            for (int i = 0; i < 8; i++) {
                int c = tid + (i << 8);
                int op = c >> 9, cc = c & 511;
                int row = cc >> 2, kc = cc & 3;
                uint32_t dst = sbase + stoff + (uint32_t)(op * 10240 + row * 80 + kc * 16);
                const char* src = (const char*)(gsrc[op] + (size_t)row * K + k0) + kc * 16;
                CP_ASYNC16(dst, src);
            }
            CP_COMMIT();
        }

        const uint32_t base = sbase + (uint32_t)(st * 40960);
#pragma unroll
        for (int t = 0; t < 2; t++) {
            uint32_t ahi[4][4], alo[4][4], bhi[4][2], blo[4][2];
#pragma unroll
            for (int mf = 0; mf < 4; mf++) {
                int r = wm * 64 + mf * 16 + (lane & 15);
                uint32_t ad = base + (uint32_t)(r * 80 + t * 32 + ((lane >> 4) << 4));
                LDSM4(ahi[mf], ad);
                LDSM4(alo[mf], ad + 10240);
            }
#pragma unroll
            for (int g = 0; g < 2; g++) {
                int n = wn * 32 + g * 16 + (lane & 15);
                uint32_t bd = base + 20480u + (uint32_t)(n * 80 + t * 32 + ((lane >> 4) << 4));
                uint32_t h4[4], l4[4];
                LDSM4(h4, bd);
                LDSM4(l4, bd + 10240);
                bhi[2 * g][0]     = h4[0]; bhi[2 * g][1]     = h4[2];
                bhi[2 * g + 1][0] = h4[1]; bhi[2 * g + 1][1] = h4[3];
                blo[2 * g][0]     = l4[0]; blo[2 * g][1]     = l4[2];
                blo[2 * g + 1][0] = l4[1]; blo[2 * g + 1][1] = l4[3];
            }
#pragma unroll
            for (int mf = 0; mf < 4; mf++)
#pragma unroll
                for (int nf = 0; nf < 4; nf++) {
                    MMA_BF16(acc[mf][nf], ahi[mf], bhi[nf]);
                    MMA_BF16(acc[mf][nf], ahi[mf], blo[nf]);
                    MMA_BF16(acc[mf][nf], alo[mf], bhi[nf]);
                }
        }
        CP_WAIT0();
        __syncthreads();
    }

    const int qr = lane >> 2;
    const int qc = (lane & 3) * 2;
#pragma unroll
    for (int mf = 0; mf < 4; mf++)
#pragma unroll
        for (int nf = 0; nf < 4; nf++) {
            int r = row0 + wm * 64 + mf * 16 + qr;
            int cI = col0 + wn * 32 + nf * 8 + qc;
            float2 v0 = make_float2(acc[mf][nf][0], acc[mf][nf][1]);
            float2 v1 = make_float2(acc[mf][nf][2], acc[mf][nf][3]);
            *(float2*)(C + (size_t)r * N + cI)       = v0;
            *(float2*)(C + (size_t)(r + 8) * N + cI) = v1;
        }
}

// ===========================================================================
// bf16 split conversions
// ===========================================================================
__global__ void split_kernel(const float* __restrict__ src,
                             __nv_bfloat16* __restrict__ hi,
                             __nv_bfloat16* __restrict__ lo, int n4)
{
    int i = blockIdx.x * blockDim.x + threadIdx.x;
    if (i >= n4) return;
    float4 v = *(const float4*)(src + (size_t)i * 4);
    float f[4] = {v.x, v.y, v.z, v.w};
    __nv_bfloat16 h[4], l[4];
#pragma unroll
    for (int j = 0; j < 4; j++) {
        h[j] = __float2bfloat16(f[j]);
        l[j] = __float2bfloat16(f[j] - __bfloat162float(h[j]));
    }
    *(__nv_bfloat162*)(hi + (size_t)i * 4)     = __nv_bfloat162(h[0], h[1]);
    *(__nv_bfloat162*)(hi + (size_t)i * 4 + 2) = __nv_bfloat162(h[2], h[3]);
    *(__nv_bfloat162*)(lo + (size_t)i * 4)     = __nv_bfloat162(l[0], l[1]);
    *(__nv_bfloat162*)(lo + (size_t)i * 4 + 2) = __nv_bfloat162(l[2], l[3]);
}

__global__ void splitT_kernel(const float* __restrict__ W,
                              __nv_bfloat16* __restrict__ hi,
                              __nv_bfloat16* __restrict__ lo, int K, int N)
{
    __shared__ float t[32][33];
    const int n0 = blockIdx.x * 32;
    const int k0 = blockIdx.y * 32;
    const int tx = threadIdx.x, ty = threadIdx.y;
#pragma unroll
    for (int j = 0; j < 4; j++)
        t[ty + j * 8][tx] = W[(size_t)(k0 + ty + j * 8) * N + n0 + tx];
    __syncthreads();
#pragma unroll
    for (int j = 0; j < 4; j++) {
        float v = t[tx][ty + j * 8];
        __nv_bfloat16 h = __float2bfloat16(v);
        __nv_bfloat16 l = __float2bfloat16(v - __bfloat162float(h));
        size_t o = (size_t)(n0 + ty + j * 8) * K + k0 + tx;
        hi[o] = h;
        lo[o] = l;
    }
}

// ===========================================================================
// RoPE: invf table once (expensive double pow), trig inline in split.
// ===========================================================================
__global__ void invf_init_kernel()
{
    int i = threadIdx.x;   // 128 threads
    double ex = (double)(2 * i) / 256.0;
    float pf = (float)pow(10000.0, ex);
    g_invf[i] = __fdiv_rn(1.0f, pf);
}

__global__ void rope_split_kernel(const float* __restrict__ buf, int nheads,
                                  __nv_bfloat16* __restrict__ hi,
                                  __nv_bfloat16* __restrict__ lo)
{
    int l = WIN + blockIdx.x;
    int i = threadIdx.x;        // 0..127
    float ang = (float)l * g_invf[i];          // fp32, as in jnp.outer
    double a  = (double)ang;
    double kq = rint(a * 0.15915494309189535);
    double r  = fma(-kq, 6.283185307179586, a);
    float s, c;
    __sincosf((float)r, &s, &c);               // accurate for |r|<=pi
    int nd = nheads * DH;
    for (int h = 0; h < nheads; h++) {
        size_t base = (size_t)l * nd + (size_t)h * DH;
        float x1 = buf[base + i];
        float x2 = buf[base + i + 128];
        float y1 = x1 * c - x2 * s;
        float y2 = x2 * c + x1 * s;
        size_t o = (size_t)(l - WIN) * nd + (size_t)h * DH;
        __nv_bfloat16 h1 = __float2bfloat16(y1);
        __nv_bfloat16 h2 = __float2bfloat16(y2);
        hi[o + i]       = h1;
        hi[o + i + 128] = h2;
        lo[o + i]       = __float2bfloat16(y1 - __bfloat162float(h1));
        lo[o + i + 128] = __float2bfloat16(y2 - __bfloat162float(h2));
    }
}

// V transpose-split: g_v rows >= WIN -> Vt[hkv][d][k-WIN] bf16 hi/lo.
__global__ void vt_split_kernel()
{
    __shared__ float t[32][33];
    const int k0  = blockIdx.x * 32;
    const int d0  = blockIdx.y * 32;
    const int hkv = blockIdx.z;
    const int tx = threadIdx.x, ty = threadIdx.y;
#pragma unroll
    for (int j = 0; j < 4; j++)
        t[ty + j * 8][tx] = g_v[(size_t)(WIN + k0 + ty + j * 8) * KDIM + hkv * DH + d0 + tx];
    __syncthreads();
#pragma unroll
    for (int j = 0; j < 4; j++) {
        float v = t[tx][ty + j * 8];
        __nv_bfloat16 h = __float2bfloat16(v);
        __nv_bfloat16 l = __float2bfloat16(v - __bfloat162float(h));
        size_t o = (size_t)hkv * DH * WIN + (size_t)(d0 + ty + j * 8) * WIN + k0 + tx;
        g_vthi[o] = h;
        g_vtlo[o] = l;
    }
}

// ===========================================================================
// lowq path via linearity: vmean = (sum_l x_l) @ wv / 4096
// ===========================================================================
__global__ void xsum_part_kernel(const float* __restrict__ x)
{
    int j = blockIdx.x * 256 + threadIdx.x;
    if (j >= HID) return;
    int p = blockIdx.y;             // 16 chunks of 256 rows
    float s = 0.0f;
    for (int l = p * 256; l < (p + 1) * 256; l++)
        s += x[(size_t)l * HID + j];
    g_xpart[p * HID + j] = s;
}
__global__ void xsum_comb_kernel()
{
    int j = blockIdx.x * 256 + threadIdx.x;
    if (j >= HID) return;
    float s = 0.0f;
#pragma unroll
    for (int p = 0; p < 16; p++) s += g_xpart[p * HID + j];
    g_xsum[j] = s;
}
__global__ void vmean_part_kernel(const float* __restrict__ wv)
{
    int d = blockIdx.x * 256 + threadIdx.x;
    if (d >= KDIM) return;
    int p = blockIdx.y;             // 8 chunks of 288
    float s = 0.0f;
    for (int i = p * 288; i < (p + 1) * 288; i++)
        s = fmaf(g_xsum[i], wv[(size_t)i * KDIM + d], s);
    g_vpart[p * KDIM + d] = s;
}
__global__ void vmean_comb_kernel()
{
    int d = blockIdx.x * 256 + threadIdx.x;
    if (d >= KDIM) return;
    float s = 0.0f;
#pragma unroll
    for (int p = 0; p < 8; p++) s += g_vpart[p * KDIM + d];
    g_vmean[d] = s * (1.0f / 4096.0f);
}
__global__ void lowout_part_kernel(const float* __restrict__ wo)
{
    int j = blockIdx.x * 256 + threadIdx.x;
    if (j >= HID) return;
    int p = blockIdx.y;             // 8 chunks of 256 i's
    float s = 0.0f;
    for (int i = p * 256; i < (p + 1) * 256; i++) {
        int h = i >> 8, d = i & 255;
        float r = g_vmean[(h >> 1) * 256 + d];
        s = fmaf(r, wo[(size_t)i * HID + j], s);
    }
    g_lowpart[p * HID + j] = s;
}
__global__ void lowout_comb_kernel()
{
    int j = blockIdx.x * 256 + threadIdx.x;
    if (j >= HID) return;
    float s = 0.0f;
#pragma unroll
    for (int p = 0; p < 8; p++) s += g_lowpart[p * HID + j];
    g_lowrow[j] = s;
}
__global__ void lowfill_kernel(float* __restrict__ out)
{
    int idx = blockIdx.x * blockDim.x + threadIdx.x;
    if (idx >= WIN * HID) return;
    out[idx] = g_lowrow[idx % HID];
}

// ===========================================================================
// Accurate 50*tanh(x/50) via expm1f
// ===========================================================================
__device__ __forceinline__ float softcap50(float s)
{
    float x = __fdiv_rn(s * SCALEF, 50.0f);
    x = fminf(fmaxf(x, -15.0f), 15.0f);
    float e = expm1f(2.0f * x);
    return 50.0f * __fdiv_rn(e, e + 2.0f);
}

// ===========================================================================
// Tensor-core flash attention (q >= 2048), pipelined.
// SMEM map (bytes):
//   QHI 0 (64x528)     QLO 33792            [end 67584]
//   KHI 67584 (32x528) KLO 84480            [end 101376]
//   VT buf0: HI 101376, LO 121856           [end 142336]
//   VT buf1: HI 142336, LO 162816           [end 183296]
//   SS 183296 (64x36x4=9216)                [end 192512]
//   PHI 192512 (64x80) PLO 197632           [end 202752]
//   m 202752  l 203008  c 203264            [total 203520]
// Pipeline: VT(t+1) prefetched at top; K(t+1) issued after QK consumes K(t).
// Softmax parallel: 4 threads/row, shfl_xor reductions.
// ===========================================================================
__global__ __launch_bounds__(256) void flash_mma(
    const __nv_bfloat16* __restrict__ Qhi, const __nv_bfloat16* __restrict__ Qlo,
    const __nv_bfloat16* __restrict__ Khi, const __nv_bfloat16* __restrict__ Klo,
    const __nv_bfloat16* __restrict__ Vthi, const __nv_bfloat16* __restrict__ Vtlo,
    __nv_bfloat16* __restrict__ Ohi, __nv_bfloat16* __restrict__ Olo)
{
    extern __shared__ char dsm[];
    const uint32_t sb = smem_u32(dsm);
    float* SS  = (float*)(dsm + 183296);
    float* m_s = (float*)(dsm + 202752);
    float* l_s = (float*)(dsm + 203008);
    float* c_s = (float*)(dsm + 203264);

    const int tid  = threadIdx.x;
    const int warp = tid >> 5;
    const int lane = tid & 31;
    const int h    = blockIdx.y;
    const int hkv  = h >> 1;
    const int it   = 31 - (int)blockIdx.x;
    const int q0r  = it * 64;
    const int nk   = 2 * it + 2;

    const size_t vtbase_g = (size_t)hkv * DH * WIN;

    // prologue: Q + K(0) + VT(0) as one commit group
#pragma unroll
    for (int i = 0; i < 16; i++) {
        int c = tid + (i << 8);
        int op = c >> 11, cc = c & 2047;
        int row = cc >> 5, ch = cc & 31;
        uint32_t dst = sb + (uint32_t)(op * 33792 + row * 528 + ch * 16);
        const char* src = (const char*)((op ? Qlo : Qhi)
                          + (size_t)(q0r + row) * QDIM + h * DH) + ch * 16;
        CP_ASYNC16(dst, src);
    }
#pragma unroll
    for (int i = 0; i < 8; i++) {
        int c = tid + (i << 8);
        int op = c >> 10, cc = c & 1023;
        int row = cc >> 5, ch = cc & 31;
        uint32_t dst = sb + 67584u + (uint32_t)(op * 16896 + row * 528 + ch * 16);
        const char* src = (const char*)((op ? Klo : Khi)
                          + (size_t)row * KDIM + hkv * DH) + ch * 16;
        CP_ASYNC16(dst, src);
    }
#pragma unroll
    for (int i = 0; i < 8; i++) {
        int c = tid + (i << 8);
        int op = c >> 10, cc = c & 1023;
        int row = cc >> 2, ch = cc & 3;
        uint32_t dst = sb + 101376u + (uint32_t)(op * 20480 + row * 80 + ch * 16);
        const char* src = (const char*)((op ? Vtlo : Vthi)
                          + vtbase_g + (size_t)row * WIN) + ch * 16;
        CP_ASYNC16(dst, src);
    }
    CP_COMMIT();

    if (tid < 64) { m_s[tid] = -INFINITY; l_s[tid] = 0.0f; }

    float o[4][4][4];
#pragma unroll
    for (int a = 0; a < 4; a++)
#pragma unroll
        for (int b = 0; b < 4; b++)
#pragma unroll
            for (int c = 0; c < 4; c++) o[a][b][c] = 0.0f;

    const int wm = warp >> 1;
    const int wn = warp & 1;
    const int qr = lane >> 2, qc = (lane & 3) * 2;

    for (int t = 0; t < nk; t++) {
        // prefetch VT(t+1) into alternate buffer
        if (t + 1 < nk) {
            const int k1 = (t + 1) * 32;
            const uint32_t vtoff = 101376u + (uint32_t)(((t + 1) & 1) * 40960);
#pragma unroll
            for (int i = 0; i < 8; i++) {
                int c = tid + (i << 8);
                int op = c >> 10, cc = c & 1023;
                int row = cc >> 2, ch = cc & 3;
                uint32_t dst = sb + vtoff + (uint32_t)(op * 20480 + row * 80 + ch * 16);
                const char* src = (const char*)((op ? Vtlo : Vthi)
                                  + vtbase_g + (size_t)row * WIN + k1) + ch * 16;
                CP_ASYNC16(dst, src);
            }
            CP_COMMIT();
            CP_WAIT1();   // tile t (K+VT) complete; VT(t+1) in flight
        } else {
            CP_WAIT0();
        }
        __syncthreads();

        const int k0r = t * 32;

        // ---- QK^T (16q x 16k per warp over d=256) ----
        float s[2][4];
#pragma unroll
        for (int nf = 0; nf < 2; nf++)
#pragma unroll
            for (int e = 0; e < 4; e++) s[nf][e] = 0.0f;

#pragma unroll
        for (int ds = 0; ds < 16; ds++) {
            uint32_t ah[4], al[4], kh4[4], kl4[4];
            uint32_t qa = sb + (uint32_t)((wm * 16 + (lane & 15)) * 528
                           + ds * 32 + ((lane >> 4) << 4));
            LDSM4(ah, qa);
            LDSM4(al, qa + 33792);
            uint32_t ka = sb + 67584u + (uint32_t)((wn * 16 + (lane & 15)) * 528
                           + ds * 32 + ((lane >> 4) << 4));
            LDSM4(kh4, ka);
            LDSM4(kl4, ka + 16896);
            uint32_t bh0[2] = {kh4[0], kh4[2]}, bh1[2] = {kh4[1], kh4[3]};
            uint32_t bl0[2] = {kl4[0], kl4[2]}, bl1[2] = {kl4[1], kl4[3]};
            MMA_BF16(s[0], ah, bh0); MMA_BF16(s[0], ah, bl0); MMA_BF16(s[0], al, bh0);
            MMA_BF16(s[1], ah, bh1); MMA_BF16(s[1], ah, bl1); MMA_BF16(s[1], al, bh1);
        }

#pragma unroll
        for (int nf = 0; nf < 2; nf++)
#pragma unroll
            for (int e = 0; e < 4; e++) {
                int r = wm * 16 + qr + ((e >> 1) * 8);
                int cI = wn * 16 + nf * 8 + qc + (e & 1);
                float v = softcap50(s[nf][e]);
                if (k0r + cI > q0r + r) v = NEGC;
                SS[r * 36 + cI] = v;
            }
        __syncthreads();   // SS ready; K(t) fully consumed

        // issue K(t+1) now (overlaps softmax + PV)
        if (t + 1 < nk) {
            const int k1 = (t + 1) * 32;
#pragma unroll
            for (int i = 0; i < 8; i++) {
                int c = tid + (i << 8);
                int op = c >> 10, cc = c & 1023;
                int row = cc >> 5, ch = cc & 31;
                uint32_t dst = sb + 67584u + (uint32_t)(op * 16896 + row * 528 + ch * 16);
                const char* src = (const char*)((op ? Klo : Khi)
                                  + (size_t)(k1 + row) * KDIM + hkv * DH) + ch * 16;
                CP_ASYNC16(dst, src);
            }
            CP_COMMIT();
        }

        // ---- parallel softmax: 4 threads per row ----
        {
            int r = tid >> 2, sub = tid & 3;
            const float* rp = SS + r * 36 + sub * 8;
            float mo = m_s[r];
            float v[8];
#pragma unroll
            for (int j = 0; j < 8; j++) v[j] = rp[j];
            float mx8 = v[0];
#pragma unroll
            for (int j = 1; j < 8; j++) mx8 = fmaxf(mx8, v[j]);
            mx8 = fmaxf(mx8, __shfl_xor_sync(0xFFFFFFFFu, mx8, 1));
            mx8 = fmaxf(mx8, __shfl_xor_sync(0xFFFFFFFFu, mx8, 2));
            float mx = fmaxf(mo, mx8);
            float corr = expf(mo - mx);
            __nv_bfloat16* ph = (__nv_bfloat16*)(dsm + 192512) + r * 40 + sub * 8;
            __nv_bfloat16* pl = (__nv_bfloat16*)(dsm + 197632) + r * 40 + sub * 8;
            float sum = 0.0f;
#pragma unroll
            for (int j = 0; j < 8; j++) {
                float p = expf(v[j] - mx);
                sum += p;
                __nv_bfloat16 hh = __float2bfloat16(p);
                ph[j] = hh;
                pl[j] = __float2bfloat16(p - __bfloat162float(hh));
            }
            sum += __shfl_xor_sync(0xFFFFFFFFu, sum, 1);
            sum += __shfl_xor_sync(0xFFFFFFFFu, sum, 2);
            if (sub == 0) {
                m_s[r] = mx;
                l_s[r] = fmaf(l_s[r], corr, sum);
                c_s[r] = corr;
            }
        }
        __syncthreads();   // P + c_s ready

        // ---- rescale O ----
#pragma unroll
        for (int mf = 0; mf < 4; mf++) {
            float c0 = c_s[mf * 16 + qr];
            float c1 = c_s[mf * 16 + qr + 8];
#pragma unroll
            for (int nf = 0; nf < 4; nf++) {
                o[mf][nf][0] *= c0; o[mf][nf][1] *= c0;
                o[mf][nf][2] *= c1; o[mf][nf][3] *= c1;
            }
        }

        // ---- PV: warp owns d-slice [warp*32, +32); VT from buffer t&1 ----
        const uint32_t vtb = sb + 101376u + (uint32_t)((t & 1) * 40960);
#pragma unroll
        for (int ks = 0; ks < 2; ks++) {
            uint32_t aph[4][4], apl[4][4], bh[4][2], bl[4][2];
#pragma unroll
            for (int mf = 0; mf < 4; mf++) {
                uint32_t pa = sb + 192512u + (uint32_t)((mf * 16 + (lane & 15)) * 80
                               + ks * 32 + ((lane >> 4) << 4));
                LDSM4(aph[mf], pa);
                LDSM4(apl[mf], pa + 5120);
            }
#pragma unroll
            for (int g = 0; g < 2; g++) {
                uint32_t va = vtb + (uint32_t)((warp * 32 + g * 16 + (lane & 15)) * 80
                               + ks * 32 + ((lane >> 4) << 4));
                uint32_t vh4[4], vl4[4];
                LDSM4(vh4, va);
                LDSM4(vl4, va + 20480);
                bh[2 * g][0]     = vh4[0]; bh[2 * g][1]     = vh4[2];
                bh[2 * g + 1][0] = vh4[1]; bh[2 * g + 1][1] = vh4[3];
                bl[2 * g][0]     = vl4[0]; bl[2 * g][1]     = vl4[2];
                bl[2 * g + 1][0] = vl4[1]; bl[2 * g + 1][1] = vl4[3];
            }
#pragma unroll
            for (int mf = 0; mf < 4; mf++)
#pragma unroll
                for (int nf = 0; nf < 4; nf++) {
                    MMA_BF16(o[mf][nf], aph[mf], bh[nf]);
                    MMA_BF16(o[mf][nf], aph[mf], bl[nf]);
                    MMA_BF16(o[mf][nf], apl[mf], bh[nf]);
                }
        }
        __syncthreads();   // before VT buffer reuse / SS/P overwrite
    }

    // ---- epilogue ----
#pragma unroll
    for (int mf = 0; mf < 4; mf++) {
        float li0 = l_s[mf * 16 + qr];
        float li1 = l_s[mf * 16 + qr + 8];
        int r0 = q0r + mf * 16 + qr;
#pragma unroll
        for (int nf = 0; nf < 4; nf++) {
            int dcol = warp * 32 + nf * 8 + qc;
            size_t o0 = (size_t)r0 * QDIM + h * DH + dcol;
            size_t o1 = (size_t)(r0 + 8) * QDIM + h * DH + dcol;
            float v00 = __fdiv_rn(o[mf][nf][0], li0);
            float v01 = __fdiv_rn(o[mf][nf][1], li0);
            float v10 = __fdiv_rn(o[mf][nf][2], li1);
            float v11 = __fdiv_rn(o[mf][nf][3], li1);
            __nv_bfloat16 h00 = __float2bfloat16(v00), h01 = __float2bfloat16(v01);
            __nv_bfloat16 h10 = __float2bfloat16(v10), h11 = __float2bfloat16(v11);
            *(__nv_bfloat162*)(Ohi + o0) = __nv_bfloat162(h00, h01);
            *(__nv_bfloat162*)(Ohi + o1) = __nv_bfloat162(h10, h11);
            *(__nv_bfloat162*)(Olo + o0) = __nv_bfloat162(
                __float2bfloat16(v00 - __bfloat162float(h00)),
                __float2bfloat16(v01 - __bfloat162float(h01)));
            *(__nv_bfloat162*)(Olo + o1) = __nv_bfloat162(
                __float2bfloat16(v10 - __bfloat162float(h10)),
                __float2bfloat16(v11 - __bfloat162float(h11)));
        }
    }
}

// ===========================================================================
extern "C" void kernel_launch(void* const* d_in, const int* in_sizes, int n_in,
                              void* d_out, int out_size)
{
    const float* x  = (const float*)d_in[0];
    const float* wq = (const float*)d_in[2];
    const float* wk = (const float*)d_in[3];
    const float* wv = (const float*)d_in[4];
    const float* wo = (const float*)d_in[5];
    float* out = (float*)d_out;

    float *pq, *pk, *pv;
    cudaGetSymbolAddress((void**)&pq, g_q);
    cudaGetSymbolAddress((void**)&pk, g_k);
    cudaGetSymbolAddress((void**)&pv, g_v);
    __nv_bfloat16 *xhi, *xlo, *ahi, *alo, *qshi, *qslo, *kshi, *kslo, *vthi, *vtlo;
    __nv_bfloat16 *wqh, *wql, *wkh, *wkl, *wvh, *wvl, *woh, *wol;
    cudaGetSymbolAddress((void**)&xhi,  g_xhi);
    cudaGetSymbolAddress((void**)&xlo,  g_xlo);
    cudaGetSymbolAddress((void**)&ahi,  g_ahi);
    cudaGetSymbolAddress((void**)&alo,  g_alo);
    cudaGetSymbolAddress((void**)&qshi, g_qhi);
    cudaGetSymbolAddress((void**)&qslo, g_qlo);
    cudaGetSymbolAddress((void**)&kshi, g_khi);
    cudaGetSymbolAddress((void**)&kslo, g_klo);
    cudaGetSymbolAddress((void**)&vthi, g_vthi);
    cudaGetSymbolAddress((void**)&vtlo, g_vtlo);
    cudaGetSymbolAddress((void**)&wqh,  g_wqhi);
    cudaGetSymbolAddress((void**)&wql,  g_wqlo);
    cudaGetSymbolAddress((void**)&wkh,  g_wkhi);
    cudaGetSymbolAddress((void**)&wkl,  g_wklo);
    cudaGetSymbolAddress((void**)&wvh,  g_wvhi);
    cudaGetSymbolAddress((void**)&wvl,  g_wvlo);
    cudaGetSymbolAddress((void**)&woh,  g_wohi);
    cudaGetSymbolAddress((void**)&wol,  g_wolo);

    dim3 blk(256);
    dim3 tb(32, 8);
    const int GEMM_SMEM  = 81920;
    const int FLASH_SMEM = 203520;
    cudaFuncSetAttribute(gemm_mma, cudaFuncAttributeMaxDynamicSharedMemorySize, GEMM_SMEM);
    cudaFuncSetAttribute(flash_mma, cudaFuncAttributeMaxDynamicSharedMemorySize, FLASH_SMEM);

    // launch index 3 = gemm_mma(Q) for ncu capture
    {
        int n4 = LSEQ * HID / 4;
        split_kernel<<<(n4 + 255) / 256, blk>>>(x, xhi, xlo, n4);              // 0
    }
    splitT_kernel<<<dim3(QDIM / 32, HID / 32), tb>>>(wq, wqh, wql, HID, QDIM); // 1
    splitT_kernel<<<dim3(HID / 32, QDIM / 32), tb>>>(wo, woh, wol, QDIM, HID); // 2
    gemm_mma<<<dim3(QDIM / 128, WIN / 128), blk, GEMM_SMEM>>>(                 // 3
        xhi + (size_t)WIN * HID, xlo + (size_t)WIN * HID, wqh, wql,
        pq + (size_t)WIN * QDIM, WIN, QDIM, HID);
    splitT_kernel<<<dim3(KDIM / 32, HID / 32), tb>>>(wk, wkh, wkl, HID, KDIM); // 4
    splitT_kernel<<<dim3(KDIM / 32, HID / 32), tb>>>(wv, wvh, wvl, HID, KDIM); // 5
    gemm_mma<<<dim3(KDIM / 128, WIN / 128), blk, GEMM_SMEM>>>(
        xhi + (size_t)WIN * HID, xlo + (size_t)WIN * HID, wkh, wkl,
        pk + (size_t)WIN * KDIM, WIN, KDIM, HID);
    gemm_mma<<<dim3(KDIM / 128, WIN / 128), blk, GEMM_SMEM>>>(                 // V pruned
        xhi + (size_t)WIN * HID, xlo + (size_t)WIN * HID, wvh, wvl,
        pv + (size_t)WIN * KDIM, WIN, KDIM, HID);

    // RoPE
    invf_init_kernel<<<1, 128>>>();
    rope_split_kernel<<<WIN, 128>>>(pq, NHQ, qshi, qslo);
    rope_split_kernel<<<WIN, 128>>>(pk, NKV, kshi, kslo);
    vt_split_kernel<<<dim3(WIN / 32, DH / 32, NKV), tb>>>();

    // lowq rows: xsum -> vmean -> lowrow -> fill
    xsum_part_kernel<<<dim3(9, 16), blk>>>(x);
    xsum_comb_kernel<<<9, blk>>>();
    vmean_part_kernel<<<dim3(4, 8), blk>>>(wv);
    vmean_comb_kernel<<<4, blk>>>();
    lowout_part_kernel<<<dim3(9, 8), blk>>>(wo);
    lowout_comb_kernel<<<9, blk>>>();
    lowfill_kernel<<<(WIN * HID + 255) / 256, blk>>>(out);

    // Flash attention (q >= 2048)
    flash_mma<<<dim3(32, NHQ), blk, FLASH_SMEM>>>(
        qshi, qslo, kshi, kslo, vthi, vtlo, ahi, alo);

    // Output projection: high rows only
    gemm_mma<<<dim3(HID / 128, WIN / 128), blk, GEMM_SMEM>>>(
        ahi, alo, woh, wol, out + (size_t)WIN * HID, WIN, HID, QDIM);
}

// round 11
// speedup vs baseline: 6.0009x; 1.0453x over previous
#include <cuda_runtime.h>
#include <cuda_bf16.h>
#include <math.h>
#include <stdint.h>

#define LSEQ 4096
#define NHQ 8
#define NKV 4
#define DH 256
#define HID 2304
#define WIN 2048
#define QDIM (NHQ*DH)   /* 2048 */
#define KDIM (NKV*DH)   /* 1024 */
#define QKVN (QDIM + 2*KDIM)  /* 4096 fused N */

#define SCALEF 0.05892556509887896f   /* 288^-0.5 */
#define NEGC  (-1.0e9f)

// fused QKV projection output (rows = l - WIN, cols = [q|k|v])
static __device__ float g_qkv[(size_t)WIN * QKVN];
static __device__ float g_vmean[KDIM];
static __device__ float g_lowrow[HID];
static __device__ float g_invf[128];
static __device__ float g_xpart[16 * HID];
static __device__ float g_xsum[HID];
static __device__ float g_vpart[8 * KDIM];
static __device__ float g_lowpart[8 * HID];

// bf16-split operands
static __device__ __nv_bfloat16 g_xhi[(size_t)LSEQ * HID];
static __device__ __nv_bfloat16 g_xlo[(size_t)LSEQ * HID];
static __device__ __nv_bfloat16 g_ahi[(size_t)WIN * QDIM];
static __device__ __nv_bfloat16 g_alo[(size_t)WIN * QDIM];
// roped, compacted (rows = l - WIN)
static __device__ __nv_bfloat16 g_qhi[(size_t)WIN * QDIM];
static __device__ __nv_bfloat16 g_qlo[(size_t)WIN * QDIM];
static __device__ __nv_bfloat16 g_khi[(size_t)WIN * KDIM];
static __device__ __nv_bfloat16 g_klo[(size_t)WIN * KDIM];
// V transposed per kv head: [hkv][d=256][k-WIN=2048]
static __device__ __nv_bfloat16 g_vthi[(size_t)NKV * DH * WIN];
static __device__ __nv_bfloat16 g_vtlo[(size_t)NKV * DH * WIN];
// weights transposed to [N][K] K-major; qkv fused [4096][2304]
static __device__ __nv_bfloat16 g_wqkvhi[(size_t)QKVN * HID];
static __device__ __nv_bfloat16 g_wqkvlo[(size_t)QKVN * HID];
static __device__ __nv_bfloat16 g_wohi[(size_t)HID * QDIM];
static __device__ __nv_bfloat16 g_wolo[(size_t)HID * QDIM];

// ===========================================================================
// Helpers (base-target PTX only)
// ===========================================================================
__device__ __forceinline__ uint32_t smem_u32(const void* p) {
    uint32_t r;
    asm("{ .reg .u64 t; cvta.to.shared.u64 t, %1; cvt.u32.u64 %0, t; }"
        : "=r"(r) : "l"(p));
    return r;
}

#define CP_ASYNC16(dst, src) \
    asm volatile("cp.async.cg.shared.global [%0], [%1], 16;" \
                 :: "r"(dst), "l"(src) : "memory")
#define CP_COMMIT()  asm volatile("cp.async.commit_group;" ::: "memory")
#define CP_WAIT0()   asm volatile("cp.async.wait_group 0;" ::: "memory")
#define CP_WAIT1()   asm volatile("cp.async.wait_group 1;" ::: "memory")

#define LDSM4(R, addr) \
    asm volatile("ldmatrix.sync.aligned.m8n8.x4.shared.b16 {%0,%1,%2,%3}, [%4];" \
        : "=r"((R)[0]), "=r"((R)[1]), "=r"((R)[2]), "=r"((R)[3]) : "r"(addr))

#define MMA_BF16(ACC, A, B) \
    asm volatile("mma.sync.aligned.m16n8k16.row.col.f32.bf16.bf16.f32 " \
        "{%0,%1,%2,%3}, {%4,%5,%6,%7}, {%8,%9}, {%0,%1,%2,%3};" \
        : "+f"((ACC)[0]), "+f"((ACC)[1]), "+f"((ACC)[2]), "+f"((ACC)[3]) \
        : "r"((A)[0]), "r"((A)[1]), "r"((A)[2]), "r"((A)[3]), \
          "r"((B)[0]), "r"((B)[1]))

// ===========================================================================
// bf16-split MMA GEMM (validated R7-R10)
// ===========================================================================
__global__ __launch_bounds__(256) void gemm_mma(
    const __nv_bfloat16* __restrict__ Ahi, const __nv_bfloat16* __restrict__ Alo,
    const __nv_bfloat16* __restrict__ Bhi, const __nv_bfloat16* __restrict__ Blo,
    float* __restrict__ C, int M, int N, int K)
{
    extern __shared__ char smdyn[];
    const uint32_t sbase = smem_u32(smdyn);
    const int tid  = threadIdx.x;
    const int warp = tid >> 5;
    const int lane = tid & 31;
    const int wm = warp >> 2;
    const int wn = warp & 3;
    const int row0 = blockIdx.y * 128;
    const int col0 = blockIdx.x * 128;

    const __nv_bfloat16* gsrc[4] = {
        Ahi + (size_t)row0 * K, Alo + (size_t)row0 * K,
        Bhi + (size_t)col0 * K, Blo + (size_t)col0 * K };

    float acc[4][4][4];
#pragma unroll
    for (int a = 0; a < 4; a++)
#pragma unroll
        for (int b = 0; b < 4; b++)
#pragma unroll
            for (int c = 0; c < 4; c++) acc[a][b][c] = 0.0f;

    const int S = K >> 5;

    {
#pragma unroll
        for (int i = 0; i < 8; i++) {
            int c = tid + (i << 8);
            int op = c >> 9, cc = c & 511;
            int row = cc >> 2, kc = cc & 3;
            uint32_t dst = sbase + (uint32_t)(op * 10240 + row * 80 + kc * 16);
            const char* src = (const char*)(gsrc[op] + (size_t)row * K) + kc * 16;
            CP_ASYNC16(dst, src);
        }
        CP_COMMIT();
        CP_WAIT0();
        __syncthreads();
    }

    for (int s = 0; s < S; s++) {
        const int st = s & 1;
        if (s + 1 < S) {
            const int k0 = (s + 1) << 5;
            const uint32_t stoff = (uint32_t)((st ^ 1) * 40960);
#pragma unroll
            for (int i = 0; i < 8; i++) {
                int c = tid + (i << 8);
                int op = c >> 9, cc = c & 511;
                int row = cc >> 2, kc = cc & 3;
                uint32_t dst = sbase + stoff + (uint32_t)(op * 10240 + row * 80 + kc * 16);
                const char* src = (const char*)(gsrc[op] + (size_t)row * K + k0) + kc * 16;
                CP_ASYNC16(dst, src);
            }
            CP_COMMIT();
        }

        const uint32_t base = sbase + (uint32_t)(st * 40960);
#pragma unroll
        for (int t = 0; t < 2; t++) {
            uint32_t ahi[4][4], alo[4][4], bhi[4][2], blo[4][2];
#pragma unroll
            for (int mf = 0; mf < 4; mf++) {
                int r = wm * 64 + mf * 16 + (lane & 15);
                uint32_t ad = base + (uint32_t)(r * 80 + t * 32 + ((lane >> 4) << 4));
                LDSM4(ahi[mf], ad);
                LDSM4(alo[mf], ad + 10240);
            }
#pragma unroll
            for (int g = 0; g < 2; g++) {
                int n = wn * 32 + g * 16 + (lane & 15);
                uint32_t bd = base + 20480u + (uint32_t)(n * 80 + t * 32 + ((lane >> 4) << 4));
                uint32_t h4[4], l4[4];
                LDSM4(h4, bd);
                LDSM4(l4, bd + 10240);
                bhi[2 * g][0]     = h4[0]; bhi[2 * g][1]     = h4[2];
                bhi[2 * g + 1][0] = h4[1]; bhi[2 * g + 1][1] = h4[3];
                blo[2 * g][0]     = l4[0]; blo[2 * g][1]     = l4[2];
                blo[2 * g + 1][0] = l4[1]; blo[2 * g + 1][1] = l4[3];
            }
#pragma unroll
            for (int mf = 0; mf < 4; mf++)
#pragma unroll
                for (int nf = 0; nf < 4; nf++) {
                    MMA_BF16(acc[mf][nf], ahi[mf], bhi[nf]);
                    MMA_BF16(acc[mf][nf], ahi[mf], blo[nf]);
                    MMA_BF16(acc[mf][nf], alo[mf], bhi[nf]);
                }
        }
        CP_WAIT0();
        __syncthreads();
    }

    const int qr = lane >> 2;
    const int qc = (lane & 3) * 2;
#pragma unroll
    for (int mf = 0; mf < 4; mf++)
#pragma unroll
        for (int nf = 0; nf < 4; nf++) {
            int r = row0 + wm * 64 + mf * 16 + qr;
            int cI = col0 + wn * 32 + nf * 8 + qc;
            float2 v0 = make_float2(acc[mf][nf][0], acc[mf][nf][1]);
            float2 v1 = make_float2(acc[mf][nf][2], acc[mf][nf][3]);
            *(float2*)(C + (size_t)r * N + cI)       = v0;
            *(float2*)(C + (size_t)(r + 8) * N + cI) = v1;
        }
}

// ===========================================================================
// bf16 split conversions
// ===========================================================================
__global__ void split_kernel(const float* __restrict__ src,
                             __nv_bfloat16* __restrict__ hi,
                             __nv_bfloat16* __restrict__ lo, int n4)
{
    int i = blockIdx.x * blockDim.x + threadIdx.x;
    if (i >= n4) return;
    float4 v = *(const float4*)(src + (size_t)i * 4);
    float f[4] = {v.x, v.y, v.z, v.w};
    __nv_bfloat16 h[4], l[4];
#pragma unroll
    for (int j = 0; j < 4; j++) {
        h[j] = __float2bfloat16(f[j]);
        l[j] = __float2bfloat16(f[j] - __bfloat162float(h[j]));
    }
    *(__nv_bfloat162*)(hi + (size_t)i * 4)     = __nv_bfloat162(h[0], h[1]);
    *(__nv_bfloat162*)(hi + (size_t)i * 4 + 2) = __nv_bfloat162(h[2], h[3]);
    *(__nv_bfloat162*)(lo + (size_t)i * 4)     = __nv_bfloat162(l[0], l[1]);
    *(__nv_bfloat162*)(lo + (size_t)i * 4 + 2) = __nv_bfloat162(l[2], l[3]);
}

// Fused transposing split of wq|wk|wv into g_wqkv [4096][2304]
__global__ void splitT_qkv_kernel(const float* __restrict__ wq,
                                  const float* __restrict__ wk,
                                  const float* __restrict__ wv)
{
    __shared__ float t[32][33];
    const int n0 = blockIdx.x * 32;     // 0..4095 (fused col)
    const int k0 = blockIdx.y * 32;     // 0..2303
    const int tx = threadIdx.x, ty = threadIdx.y;

    const float* W;
    int Nsrc, nb;
    if (n0 < QDIM)             { W = wq; Nsrc = QDIM; nb = n0; }
    else if (n0 < QDIM + KDIM) { W = wk; Nsrc = KDIM; nb = n0 - QDIM; }
    else                       { W = wv; Nsrc = KDIM; nb = n0 - QDIM - KDIM; }

#pragma unroll
    for (int j = 0; j < 4; j++)
        t[ty + j * 8][tx] = W[(size_t)(k0 + ty + j * 8) * Nsrc + nb + tx];
    __syncthreads();
#pragma unroll
    for (int j = 0; j < 4; j++) {
        float v = t[tx][ty + j * 8];
        __nv_bfloat16 h = __float2bfloat16(v);
        __nv_bfloat16 l = __float2bfloat16(v - __bfloat162float(h));
        size_t o = (size_t)(n0 + ty + j * 8) * HID + k0 + tx;
        g_wqkvhi[o] = h;
        g_wqkvlo[o] = l;
    }
}

__global__ void splitT_kernel(const float* __restrict__ W,
                              __nv_bfloat16* __restrict__ hi,
                              __nv_bfloat16* __restrict__ lo, int K, int N)
{
    __shared__ float t[32][33];
    const int n0 = blockIdx.x * 32;
    const int k0 = blockIdx.y * 32;
    const int tx = threadIdx.x, ty = threadIdx.y;
#pragma unroll
    for (int j = 0; j < 4; j++)
        t[ty + j * 8][tx] = W[(size_t)(k0 + ty + j * 8) * N + n0 + tx];
    __syncthreads();
#pragma unroll
    for (int j = 0; j < 4; j++) {
        float v = t[tx][ty + j * 8];
        __nv_bfloat16 h = __float2bfloat16(v);
        __nv_bfloat16 l = __float2bfloat16(v - __bfloat162float(h));
        size_t o = (size_t)(n0 + ty + j * 8) * K + k0 + tx;
        hi[o] = h;
        lo[o] = l;
    }
}

// ===========================================================================
// RoPE: invf table once, trig inline (double range-reduction + __sincosf)
// ===========================================================================
__global__ void invf_init_kernel()
{
    int i = threadIdx.x;
    double ex = (double)(2 * i) / 256.0;
    float pf = (float)pow(10000.0, ex);
    g_invf[i] = __fdiv_rn(1.0f, pf);
}

// reads from g_qkv (stride QKVN, column offset coloff); rows are l - WIN
__global__ void rope_split_kernel(int coloff, int nheads,
                                  __nv_bfloat16* __restrict__ hi,
                                  __nv_bfloat16* __restrict__ lo)
{
    int row = blockIdx.x;          // 0..2047
    int l = WIN + row;
    int i = threadIdx.x;           // 0..127
    float ang = (float)l * g_invf[i];
    double a  = (double)ang;
    double kq = rint(a * 0.15915494309189535);
    double r  = fma(-kq, 6.283185307179586, a);
    float s, c;
    __sincosf((float)r, &s, &c);
    int nd = nheads * DH;
    for (int h = 0; h < nheads; h++) {
        size_t base = (size_t)row * QKVN + coloff + (size_t)h * DH;
        float x1 = g_qkv[base + i];
        float x2 = g_qkv[base + i + 128];
        float y1 = x1 * c - x2 * s;
        float y2 = x2 * c + x1 * s;
        size_t o = (size_t)row * nd + (size_t)h * DH;
        __nv_bfloat16 h1 = __float2bfloat16(y1);
        __nv_bfloat16 h2 = __float2bfloat16(y2);
        hi[o + i]       = h1;
        hi[o + i + 128] = h2;
        lo[o + i]       = __float2bfloat16(y1 - __bfloat162float(h1));
        lo[o + i + 128] = __float2bfloat16(y2 - __bfloat162float(h2));
    }
}

// V transpose-split from g_qkv cols [3072..4096) -> Vt[hkv][d][k] bf16 hi/lo
__global__ void vt_split_kernel()
{
    __shared__ float t[32][33];
    const int k0  = blockIdx.x * 32;    // relative key
    const int d0  = blockIdx.y * 32;
    const int hkv = blockIdx.z;
    const int tx = threadIdx.x, ty = threadIdx.y;
#pragma unroll
    for (int j = 0; j < 4; j++)
        t[ty + j * 8][tx] = g_qkv[(size_t)(k0 + ty + j * 8) * QKVN
                                  + QDIM + KDIM + hkv * DH + d0 + tx];
    __syncthreads();
#pragma unroll
    for (int j = 0; j < 4; j++) {
        float v = t[tx][ty + j * 8];
        __nv_bfloat16 h = __float2bfloat16(v);
        __nv_bfloat16 l = __float2bfloat16(v - __bfloat162float(h));
        size_t o = (size_t)hkv * DH * WIN + (size_t)(d0 + ty + j * 8) * WIN + k0 + tx;
        g_vthi[o] = h;
        g_vtlo[o] = l;
    }
}

// ===========================================================================
// lowq path via linearity: vmean = (sum_l x_l) @ wv / 4096
// ===========================================================================
__global__ void xsum_part_kernel(const float* __restrict__ x)
{
    int j = blockIdx.x * 256 + threadIdx.x;
    if (j >= HID) return;
    int p = blockIdx.y;
    float s = 0.0f;
    for (int l = p * 256; l < (p + 1) * 256; l++)
        s += x[(size_t)l * HID + j];
    g_xpart[p * HID + j] = s;
}
__global__ void xsum_comb_kernel()
{
    int j = blockIdx.x * 256 + threadIdx.x;
    if (j >= HID) return;
    float s = 0.0f;
#pragma unroll
    for (int p = 0; p < 16; p++) s += g_xpart[p * HID + j];
    g_xsum[j] = s;
}
__global__ void vmean_part_kernel(const float* __restrict__ wv)
{
    int d = blockIdx.x * 256 + threadIdx.x;
    if (d >= KDIM) return;
    int p = blockIdx.y;
    float s = 0.0f;
    for (int i = p * 288; i < (p + 1) * 288; i++)
        s = fmaf(g_xsum[i], wv[(size_t)i * KDIM + d], s);
    g_vpart[p * KDIM + d] = s;
}
__global__ void vmean_comb_kernel()
{
    int d = blockIdx.x * 256 + threadIdx.x;
    if (d >= KDIM) return;
    float s = 0.0f;
#pragma unroll
    for (int p = 0; p < 8; p++) s += g_vpart[p * KDIM + d];
    g_vmean[d] = s * (1.0f / 4096.0f);
}
__global__ void lowout_part_kernel(const float* __restrict__ wo)
{
    int j = blockIdx.x * 256 + threadIdx.x;
    if (j >= HID) return;
    int p = blockIdx.y;
    float s = 0.0f;
    for (int i = p * 256; i < (p + 1) * 256; i++) {
        int h = i >> 8, d = i & 255;
        float r = g_vmean[(h >> 1) * 256 + d];
        s = fmaf(r, wo[(size_t)i * HID + j], s);
    }
    g_lowpart[p * HID + j] = s;
}
__global__ void lowout_comb_kernel()
{
    int j = blockIdx.x * 256 + threadIdx.x;
    if (j >= HID) return;
    float s = 0.0f;
#pragma unroll
    for (int p = 0; p < 8; p++) s += g_lowpart[p * HID + j];
    g_lowrow[j] = s;
}
__global__ void lowfill_kernel(float* __restrict__ out)
{
    int idx = blockIdx.x * blockDim.x + threadIdx.x;
    if (idx >= WIN * HID) return;
    out[idx] = g_lowrow[idx % HID];
}

// ===========================================================================
// Fast accurate softcap: 50*tanh(x/50) with tanh = (e^{2x}-1)/(e^{2x}+1),
// e via MUFU-backed __expf (~2^-22 rel err -> logit error ~2.5e-6).
// ===========================================================================
__device__ __forceinline__ float softcap50(float s)
{
    float x = __fdiv_rn(s * SCALEF, 50.0f);
    x = fminf(fmaxf(x, -15.0f), 15.0f);
    float e = __expf(2.0f * x);
    return 50.0f * __fdiv_rn(e - 1.0f, e + 1.0f);
}

// ===========================================================================
// Tensor-core flash attention (q >= 2048), pipelined (validated R10).
// ===========================================================================
__global__ __launch_bounds__(256) void flash_mma(
    const __nv_bfloat16* __restrict__ Qhi, const __nv_bfloat16* __restrict__ Qlo,
    const __nv_bfloat16* __restrict__ Khi, const __nv_bfloat16* __restrict__ Klo,
    const __nv_bfloat16* __restrict__ Vthi, const __nv_bfloat16* __restrict__ Vtlo,
    __nv_bfloat16* __restrict__ Ohi, __nv_bfloat16* __restrict__ Olo)
{
    extern __shared__ char dsm[];
    const uint32_t sb = smem_u32(dsm);
    float* SS  = (float*)(dsm + 183296);
    float* m_s = (float*)(dsm + 202752);
    float* l_s = (float*)(dsm + 203008);
    float* c_s = (float*)(dsm + 203264);

    const int tid  = threadIdx.x;
    const int warp = tid >> 5;
    const int lane = tid & 31;
    const int h    = blockIdx.y;
    const int hkv  = h >> 1;
    const int it   = 31 - (int)blockIdx.x;
    const int q0r  = it * 64;
    const int nk   = 2 * it + 2;

    const size_t vtbase_g = (size_t)hkv * DH * WIN;

#pragma unroll
    for (int i = 0; i < 16; i++) {
        int c = tid + (i << 8);
        int op = c >> 11, cc = c & 2047;
        int row = cc >> 5, ch = cc & 31;
        uint32_t dst = sb + (uint32_t)(op * 33792 + row * 528 + ch * 16);
        const char* src = (const char*)((op ? Qlo : Qhi)
                          + (size_t)(q0r + row) * QDIM + h * DH) + ch * 16;
        CP_ASYNC16(dst, src);
    }
#pragma unroll
    for (int i = 0; i < 8; i++) {
        int c = tid + (i << 8);
        int op = c >> 10, cc = c & 1023;
        int row = cc >> 5, ch = cc & 31;
        uint32_t dst = sb + 67584u + (uint32_t)(op * 16896 + row * 528 + ch * 16);
        const char* src = (const char*)((op ? Klo : Khi)
                          + (size_t)row * KDIM + hkv * DH) + ch * 16;
        CP_ASYNC16(dst, src);
    }
#pragma unroll
    for (int i = 0; i < 8; i++) {
        int c = tid + (i << 8);
        int op = c >> 10, cc = c & 1023;
        int row = cc >> 2, ch = cc & 3;
        uint32_t dst = sb + 101376u + (uint32_t)(op * 20480 + row * 80 + ch * 16);
        const char* src = (const char*)((op ? Vtlo : Vthi)
                          + vtbase_g + (size_t)row * WIN) + ch * 16;
        CP_ASYNC16(dst, src);
    }
    CP_COMMIT();

    if (tid < 64) { m_s[tid] = -INFINITY; l_s[tid] = 0.0f; }

    float o[4][4][4];
#pragma unroll
    for (int a = 0; a < 4; a++)
#pragma unroll
        for (int b = 0; b < 4; b++)
#pragma unroll
            for (int c = 0; c < 4; c++) o[a][b][c] = 0.0f;

    const int wm = warp >> 1;
    const int wn = warp & 1;
    const int qr = lane >> 2, qc = (lane & 3) * 2;

    for (int t = 0; t < nk; t++) {
        if (t + 1 < nk) {
            const int k1 = (t + 1) * 32;
            const uint32_t vtoff = 101376u + (uint32_t)(((t + 1) & 1) * 40960);
#pragma unroll
            for (int i = 0; i < 8; i++) {
                int c = tid + (i << 8);
                int op = c >> 10, cc = c & 1023;
                int row = cc >> 2, ch = cc & 3;
                uint32_t dst = sb + vtoff + (uint32_t)(op * 20480 + row * 80 + ch * 16);
                const char* src = (const char*)((op ? Vtlo : Vthi)
                                  + vtbase_g + (size_t)row * WIN + k1) + ch * 16;
                CP_ASYNC16(dst, src);
            }
            CP_COMMIT();
            CP_WAIT1();
        } else {
            CP_WAIT0();
        }
        __syncthreads();

        const int k0r = t * 32;

        float s[2][4];
#pragma unroll
        for (int nf = 0; nf < 2; nf++)
#pragma unroll
            for (int e = 0; e < 4; e++) s[nf][e] = 0.0f;

#pragma unroll
        for (int ds = 0; ds < 16; ds++) {
            uint32_t ah[4], al[4], kh4[4], kl4[4];
            uint32_t qa = sb + (uint32_t)((wm * 16 + (lane & 15)) * 528
                           + ds * 32 + ((lane >> 4) << 4));
            LDSM4(ah, qa);
            LDSM4(al, qa + 33792);
            uint32_t ka = sb + 67584u + (uint32_t)((wn * 16 + (lane & 15)) * 528
                           + ds * 32 + ((lane >> 4) << 4));
            LDSM4(kh4, ka);
            LDSM4(kl4, ka + 16896);
            uint32_t bh0[2] = {kh4[0], kh4[2]}, bh1[2] = {kh4[1], kh4[3]};
            uint32_t bl0[2] = {kl4[0], kl4[2]}, bl1[2] = {kl4[1], kl4[3]};
            MMA_BF16(s[0], ah, bh0); MMA_BF16(s[0], ah, bl0); MMA_BF16(s[0], al, bh0);
            MMA_BF16(s[1], ah, bh1); MMA_BF16(s[1], ah, bl1); MMA_BF16(s[1], al, bh1);
        }

#pragma unroll
        for (int nf = 0; nf < 2; nf++)
#pragma unroll
            for (int e = 0; e < 4; e++) {
                int r = wm * 16 + qr + ((e >> 1) * 8);
                int cI = wn * 16 + nf * 8 + qc + (e & 1);
                float v = softcap50(s[nf][e]);
                if (k0r + cI > q0r + r) v = NEGC;
                SS[r * 36 + cI] = v;
            }
        __syncthreads();

        if (t + 1 < nk) {
            const int k1 = (t + 1) * 32;
#pragma unroll
            for (int i = 0; i < 8; i++) {
                int c = tid + (i << 8);
                int op = c >> 10, cc = c & 1023;
                int row = cc >> 5, ch = cc & 31;
                uint32_t dst = sb + 67584u + (uint32_t)(op * 16896 + row * 528 + ch * 16);
                const char* src = (const char*)((op ? Klo : Khi)
                                  + (size_t)(k1 + row) * KDIM + hkv * DH) + ch * 16;
                CP_ASYNC16(dst, src);
            }
            CP_COMMIT();
        }

        {
            int r = tid >> 2, sub = tid & 3;
            const float* rp = SS + r * 36 + sub * 8;
            float mo = m_s[r];
            float v[8];
#pragma unroll
            for (int j = 0; j < 8; j++) v[j] = rp[j];
            float mx8 = v[0];
#pragma unroll
            for (int j = 1; j < 8; j++) mx8 = fmaxf(mx8, v[j]);
            mx8 = fmaxf(mx8, __shfl_xor_sync(0xFFFFFFFFu, mx8, 1));
            mx8 = fmaxf(mx8, __shfl_xor_sync(0xFFFFFFFFu, mx8, 2));
            float mx = fmaxf(mo, mx8);
            float corr = expf(mo - mx);
            __nv_bfloat16* ph = (__nv_bfloat16*)(dsm + 192512) + r * 40 + sub * 8;
            __nv_bfloat16* pl = (__nv_bfloat16*)(dsm + 197632) + r * 40 + sub * 8;
            float sum = 0.0f;
#pragma unroll
            for (int j = 0; j < 8; j++) {
                float p = expf(v[j] - mx);
                sum += p;
                __nv_bfloat16 hh = __float2bfloat16(p);
                ph[j] = hh;
                pl[j] = __float2bfloat16(p - __bfloat162float(hh));
            }
            sum += __shfl_xor_sync(0xFFFFFFFFu, sum, 1);
            sum += __shfl_xor_sync(0xFFFFFFFFu, sum, 2);
            if (sub == 0) {
                m_s[r] = mx;
                l_s[r] = fmaf(l_s[r], corr, sum);
                c_s[r] = corr;
            }
        }
        __syncthreads();

#pragma unroll
        for (int mf = 0; mf < 4; mf++) {
            float c0 = c_s[mf * 16 + qr];
            float c1 = c_s[mf * 16 + qr + 8];
#pragma unroll
            for (int nf = 0; nf < 4; nf++) {
                o[mf][nf][0] *= c0; o[mf][nf][1] *= c0;
                o[mf][nf][2] *= c1; o[mf][nf][3] *= c1;
            }
        }

        const uint32_t vtb = sb + 101376u + (uint32_t)((t & 1) * 40960);
#pragma unroll
        for (int ks = 0; ks < 2; ks++) {
            uint32_t aph[4][4], apl[4][4], bh[4][2], bl[4][2];
#pragma unroll
            for (int mf = 0; mf < 4; mf++) {
                uint32_t pa = sb + 192512u + (uint32_t)((mf * 16 + (lane & 15)) * 80
                               + ks * 32 + ((lane >> 4) << 4));
                LDSM4(aph[mf], pa);
                LDSM4(apl[mf], pa + 5120);
            }
#pragma unroll
            for (int g = 0; g < 2; g++) {
                uint32_t va = vtb + (uint32_t)((warp * 32 + g * 16 + (lane & 15)) * 80
                               + ks * 32 + ((lane >> 4) << 4));
                uint32_t vh4[4], vl4[4];
                LDSM4(vh4, va);
                LDSM4(vl4, va + 20480);
                bh[2 * g][0]     = vh4[0]; bh[2 * g][1]     = vh4[2];
                bh[2 * g + 1][0] = vh4[1]; bh[2 * g + 1][1] = vh4[3];
                bl[2 * g][0]     = vl4[0]; bl[2 * g][1]     = vl4[2];
                bl[2 * g + 1][0] = vl4[1]; bl[2 * g + 1][1] = vl4[3];
            }
#pragma unroll
            for (int mf = 0; mf < 4; mf++)
#pragma unroll
                for (int nf = 0; nf < 4; nf++) {
                    MMA_BF16(o[mf][nf], aph[mf], bh[nf]);
                    MMA_BF16(o[mf][nf], aph[mf], bl[nf]);
                    MMA_BF16(o[mf][nf], apl[mf], bh[nf]);
                }
        }
        __syncthreads();
    }

#pragma unroll
    for (int mf = 0; mf < 4; mf++) {
        float li0 = l_s[mf * 16 + qr];
        float li1 = l_s[mf * 16 + qr + 8];
        int r0 = q0r + mf * 16 + qr;
#pragma unroll
        for (int nf = 0; nf < 4; nf++) {
            int dcol = warp * 32 + nf * 8 + qc;
            size_t o0 = (size_t)r0 * QDIM + h * DH + dcol;
            size_t o1 = (size_t)(r0 + 8) * QDIM + h * DH + dcol;
            float v00 = __fdiv_rn(o[mf][nf][0], li0);
            float v01 = __fdiv_rn(o[mf][nf][1], li0);
            float v10 = __fdiv_rn(o[mf][nf][2], li1);
            float v11 = __fdiv_rn(o[mf][nf][3], li1);
            __nv_bfloat16 h00 = __float2bfloat16(v00), h01 = __float2bfloat16(v01);
            __nv_bfloat16 h10 = __float2bfloat16(v10), h11 = __float2bfloat16(v11);
            *(__nv_bfloat162*)(Ohi + o0) = __nv_bfloat162(h00, h01);
            *(__nv_bfloat162*)(Ohi + o1) = __nv_bfloat162(h10, h11);
            *(__nv_bfloat162*)(Olo + o0) = __nv_bfloat162(
                __float2bfloat16(v00 - __bfloat162float(h00)),
                __float2bfloat16(v01 - __bfloat162float(h01)));
            *(__nv_bfloat162*)(Olo + o1) = __nv_bfloat162(
                __float2bfloat16(v10 - __bfloat162float(h10)),
                __float2bfloat16(v11 - __bfloat162float(h11)));
        }
    }
}

// ===========================================================================
extern "C" void kernel_launch(void* const* d_in, const int* in_sizes, int n_in,
                              void* d_out, int out_size)
{
    const float* x  = (const float*)d_in[0];
    const float* wq = (const float*)d_in[2];
    const float* wk = (const float*)d_in[3];
    const float* wv = (const float*)d_in[4];
    const float* wo = (const float*)d_in[5];
    float* out = (float*)d_out;

    float* pqkv;
    cudaGetSymbolAddress((void**)&pqkv, g_qkv);
    __nv_bfloat16 *xhi, *xlo, *ahi, *alo, *qshi, *qslo, *kshi, *kslo, *vthi, *vtlo;
    __nv_bfloat16 *wqkvh, *wqkvl, *woh, *wol;
    cudaGetSymbolAddress((void**)&xhi,   g_xhi);
    cudaGetSymbolAddress((void**)&xlo,   g_xlo);
    cudaGetSymbolAddress((void**)&ahi,   g_ahi);
    cudaGetSymbolAddress((void**)&alo,   g_alo);
    cudaGetSymbolAddress((void**)&qshi,  g_qhi);
    cudaGetSymbolAddress((void**)&qslo,  g_qlo);
    cudaGetSymbolAddress((void**)&kshi,  g_khi);
    cudaGetSymbolAddress((void**)&kslo,  g_klo);
    cudaGetSymbolAddress((void**)&vthi,  g_vthi);
    cudaGetSymbolAddress((void**)&vtlo,  g_vtlo);
    cudaGetSymbolAddress((void**)&wqkvh, g_wqkvhi);
    cudaGetSymbolAddress((void**)&wqkvl, g_wqkvlo);
    cudaGetSymbolAddress((void**)&woh,   g_wohi);
    cudaGetSymbolAddress((void**)&wol,   g_wolo);

    dim3 blk(256);
    dim3 tb(32, 8);
    const int GEMM_SMEM  = 81920;
    const int FLASH_SMEM = 203520;
    cudaFuncSetAttribute(gemm_mma, cudaFuncAttributeMaxDynamicSharedMemorySize, GEMM_SMEM);
    cudaFuncSetAttribute(flash_mma, cudaFuncAttributeMaxDynamicSharedMemorySize, FLASH_SMEM);

    // index 3 = fused QKV gemm (ncu capture slot)
    {
        int n4 = LSEQ * HID / 4;
        split_kernel<<<(n4 + 255) / 256, blk>>>(x, xhi, xlo, n4);              // 0
    }
    splitT_qkv_kernel<<<dim3(QKVN / 32, HID / 32), tb>>>(wq, wk, wv);          // 1
    splitT_kernel<<<dim3(HID / 32, QDIM / 32), tb>>>(wo, woh, wol, QDIM, HID); // 2
    gemm_mma<<<dim3(QKVN / 128, WIN / 128), blk, GEMM_SMEM>>>(                 // 3
        xhi + (size_t)WIN * HID, xlo + (size_t)WIN * HID, wqkvh, wqkvl,
        pqkv, WIN, QKVN, HID);

    // RoPE + operand prep for flash
    invf_init_kernel<<<1, 128>>>();
    rope_split_kernel<<<WIN, 128>>>(0, NHQ, qshi, qslo);
    rope_split_kernel<<<WIN, 128>>>(QDIM, NKV, kshi, kslo);
    vt_split_kernel<<<dim3(WIN / 32, DH / 32, NKV), tb>>>();

    // lowq rows: xsum -> vmean -> lowrow -> fill
    xsum_part_kernel<<<dim3(9, 16), blk>>>(x);
    xsum_comb_kernel<<<9, blk>>>();
    vmean_part_kernel<<<dim3(4, 8), blk>>>(wv);
    vmean_comb_kernel<<<4, blk>>>();
    lowout_part_kernel<<<dim3(9, 8), blk>>>(wo);
    lowout_comb_kernel<<<9, blk>>>();
    lowfill_kernel<<<(WIN * HID + 255) / 256, blk>>>(out);

    // Flash attention (q >= 2048)
    flash_mma<<<dim3(32, NHQ), blk, FLASH_SMEM>>>(
        qshi, qslo, kshi, kslo, vthi, vtlo, ahi, alo);

    // Output projection: high rows only
    gemm_mma<<<dim3(HID / 128, WIN / 128), blk, GEMM_SMEM>>>(
        ahi, alo, woh, wol, out + (size_t)WIN * HID, WIN, HID, QDIM);
}